// round 1
// baseline (speedup 1.0000x reference)
#include <cuda_runtime.h>
#include <math.h>

// Problem constants (fixed-shape problem): B=4, L=1024, E=8, D=512, NLAYERS=2
#define Dc 512
#define Gc 4096   // B*L
#define Ec 8

// ---------------- scratch (device globals; no allocations allowed) ----------
__device__ float g_w1[Ec];          // folded expert-mixing weights
__device__ float g_s2;              // scalar bias passthrough factor
__device__ float g_Wtmp[Dc*Dc];     // W1 @ W2
__device__ float g_Wf[Dc*Dc];       // W1 @ W2 @ comb_w
__device__ float g_b1f[Dc];         // s2*(b1 @ W2) + b2
__device__ float g_bf[Dc];          // b1f @ comb_w + comb_b
__device__ float g_z0[Gc*Dc];       // weighted expert reduce
__device__ float g_y[Gc*Dc];        // gelu(z0 @ Wf + bf)

// ---------------- 1) mixing vectors from hyperedge_index --------------------
__global__ void k_mix(const int* __restrict__ he, int nnz) {
    if (threadIdx.x != 0 || blockIdx.x != 0) return;
    const int* node = he;
    const int* edge = he + nnz;
    float degn[Ec];
    float dege[64];
    for (int v = 0; v < Ec; v++) degn[v] = 0.f;
    for (int e = 0; e < 64; e++) dege[e] = 0.f;
    for (int i = 0; i < nnz; i++) {
        degn[node[i]] += 1.f;
        if (edge[i] < 64) dege[edge[i]] += 1.f;
    }
    float Dinv[Ec], Binv[64];
    for (int v = 0; v < Ec; v++) Dinv[v] = degn[v] > 0.f ? 1.f / degn[v] : 0.f;
    for (int e = 0; e < 64; e++) Binv[e] = dege[e] > 0.f ? 1.f / dege[e] : 0.f;
    // M2[v][u] = Dinv[v] * sum_e H[v,e] H[u,e] Binv[e]
    float M2[Ec][Ec];
    for (int a = 0; a < Ec; a++)
        for (int b = 0; b < Ec; b++) M2[a][b] = 0.f;
    for (int j = 0; j < nnz; j++)
        for (int i = 0; i < nnz; i++)
            if (edge[i] == edge[j])
                M2[node[j]][node[i]] += Dinv[node[j]] * Binv[edge[j]];
    // w2 = M2^T 1 / E ; w1 = M2^T w2 ; s2 = sum(w2)
    float w2[Ec], s2 = 0.f;
    for (int u = 0; u < Ec; u++) {
        float s = 0.f;
        for (int v = 0; v < Ec; v++) s += M2[v][u];
        w2[u] = s / (float)Ec;
        s2 += w2[u];
    }
    for (int t = 0; t < Ec; t++) {
        float s = 0.f;
        for (int u = 0; u < Ec; u++) s += M2[u][t] * w2[u];
        g_w1[t] = s;
    }
    g_s2 = s2;
}

// ---------------- 2) bias folds ---------------------------------------------
__global__ void k_bias1(const float* __restrict__ lin_b, const float* __restrict__ W2) {
    int n = blockIdx.x * blockDim.x + threadIdx.x;
    if (n >= Dc) return;
    float s2 = g_s2;
    float acc = 0.f;
    for (int k = 0; k < Dc; k++) acc += lin_b[k] * W2[k * Dc + n];
    g_b1f[n] = s2 * acc + lin_b[Dc + n];
}

__global__ void k_bias2(const float* __restrict__ comb_w, const float* __restrict__ comb_b) {
    int n = blockIdx.x * blockDim.x + threadIdx.x;
    if (n >= Dc) return;
    float acc = 0.f;
    for (int k = 0; k < Dc; k++) acc += g_b1f[k] * comb_w[k * Dc + n];
    g_bf[n] = acc + comb_b[n];
}

// ---------------- 3) weighted expert reduce (reads the 64MB input once) -----
__global__ void k_reduce(const float* __restrict__ X, float* __restrict__ Z) {
    // X: (G, E, D) fp32; Z: (G, D). Process float4 lanes.
    int i = blockIdx.x * blockDim.x + threadIdx.x;     // over G * (D/4)
    if (i >= Gc * (Dc / 4)) return;
    int g  = i >> 7;          // / (D/4) = /128
    int d4 = i & 127;
    const float4* xp = reinterpret_cast<const float4*>(X) + (size_t)g * Ec * (Dc / 4) + d4;
    float w[Ec];
#pragma unroll
    for (int u = 0; u < Ec; u++) w[u] = g_w1[u];
    float4 acc = make_float4(0.f, 0.f, 0.f, 0.f);
#pragma unroll
    for (int u = 0; u < Ec; u++) {
        float4 v = xp[(size_t)u * (Dc / 4)];
        acc.x = fmaf(w[u], v.x, acc.x);
        acc.y = fmaf(w[u], v.y, acc.y);
        acc.z = fmaf(w[u], v.z, acc.z);
        acc.w = fmaf(w[u], v.w, acc.w);
    }
    reinterpret_cast<float4*>(Z)[i] = acc;
}

// ---------------- 4) tiled SGEMM (row-major A[MxK] * B[KxN] + bias, opt GELU)
template <int BM, int BN, int BK, int TM, int TN, int EPI>
__global__ void sgemm(int M, int N, int K,
                      const float* __restrict__ A,
                      const float* __restrict__ B,
                      const float* __restrict__ bias,
                      float* __restrict__ C) {
    constexpr int THREADS = (BM / TM) * (BN / TN);
    __shared__ float As[BK][BM];   // A stored transposed for stride-1 reads
    __shared__ float Bs[BK][BN];
    const int tid  = threadIdx.x;
    const int brow = blockIdx.y * BM;
    const int bcol = blockIdx.x * BN;
    const int tcol = (tid % (BN / TN)) * TN;
    const int trow = (tid / (BN / TN)) * TM;

    float acc[TM][TN];
#pragma unroll
    for (int m = 0; m < TM; m++)
#pragma unroll
        for (int n = 0; n < TN; n++) acc[m][n] = 0.f;

    for (int k0 = 0; k0 < K; k0 += BK) {
        for (int i = tid; i < BM * BK / 4; i += THREADS) {
            int idx = i * 4;
            int r = idx / BK, c = idx % BK;
            float4 v = *reinterpret_cast<const float4*>(&A[(size_t)(brow + r) * K + k0 + c]);
            As[c + 0][r] = v.x;
            As[c + 1][r] = v.y;
            As[c + 2][r] = v.z;
            As[c + 3][r] = v.w;
        }
        for (int i = tid; i < BK * BN / 4; i += THREADS) {
            int idx = i * 4;
            int r = idx / BN, c = idx % BN;
            *reinterpret_cast<float4*>(&Bs[r][c]) =
                *reinterpret_cast<const float4*>(&B[(size_t)(k0 + r) * N + bcol + c]);
        }
        __syncthreads();
#pragma unroll
        for (int kk = 0; kk < BK; kk++) {
            float ra[TM], rb[TN];
#pragma unroll
            for (int m = 0; m < TM; m++) ra[m] = As[kk][trow + m];
#pragma unroll
            for (int n = 0; n < TN; n++) rb[n] = Bs[kk][tcol + n];
#pragma unroll
            for (int m = 0; m < TM; m++)
#pragma unroll
                for (int n = 0; n < TN; n++) acc[m][n] = fmaf(ra[m], rb[n], acc[m][n]);
        }
        __syncthreads();
    }

#pragma unroll
    for (int m = 0; m < TM; m++) {
#pragma unroll
        for (int n = 0; n < TN; n += 4) {
            float4 v;
            float* pv = reinterpret_cast<float*>(&v);
#pragma unroll
            for (int q = 0; q < 4; q++) {
                float x = acc[m][n + q];
                if (bias) x += bias[bcol + tcol + n + q];
                if (EPI == 1)  // exact GELU (erf form)
                    x = 0.5f * x * (1.f + erff(x * 0.70710678118654752f));
                pv[q] = x;
            }
            *reinterpret_cast<float4*>(&C[(size_t)(brow + trow + m) * N + bcol + tcol + n]) = v;
        }
    }
}

// ---------------- 5) LayerNorm over D=512 (1 block / row) -------------------
__global__ void k_ln(const float* __restrict__ Y, const float* __restrict__ gam,
                     const float* __restrict__ bet, float* __restrict__ out) {
    int row = blockIdx.x;
    const float* y = Y + (size_t)row * Dc;
    int t = threadIdx.x;  // 128 threads
    float v[4];
    float s = 0.f;
#pragma unroll
    for (int i = 0; i < 4; i++) { v[i] = y[t + i * 128]; s += v[i]; }
    __shared__ float red[4];
#pragma unroll
    for (int o = 16; o; o >>= 1) s += __shfl_xor_sync(0xffffffffu, s, o);
    if ((t & 31) == 0) red[t >> 5] = s;
    __syncthreads();
    float mu = (red[0] + red[1] + red[2] + red[3]) * (1.f / Dc);
    __syncthreads();
    float d2 = 0.f;
#pragma unroll
    for (int i = 0; i < 4; i++) { float d = v[i] - mu; d2 += d * d; }
#pragma unroll
    for (int o = 16; o; o >>= 1) d2 += __shfl_xor_sync(0xffffffffu, d2, o);
    if ((t & 31) == 0) red[t >> 5] = d2;
    __syncthreads();
    float var = (red[0] + red[1] + red[2] + red[3]) * (1.f / Dc);
    float rs = rsqrtf(var + 1e-5f);
#pragma unroll
    for (int i = 0; i < 4; i++) {
        int c = t + i * 128;
        out[(size_t)row * Dc + c] = (v[i] - mu) * rs * gam[c] + bet[c];
    }
}

// ---------------- launch -----------------------------------------------------
extern "C" void kernel_launch(void* const* d_in, const int* in_sizes, int n_in,
                              void* d_out, int out_size) {
    const float* x      = (const float*)d_in[0];  // (B,L,E,D)
    const int*   he     = (const int*)  d_in[1];  // (2, nnz)
    const float* lin_w  = (const float*)d_in[2];  // (2, D, D)
    const float* lin_b  = (const float*)d_in[3];  // (2, D)
    const float* comb_w = (const float*)d_in[4];  // (D, D)
    const float* comb_b = (const float*)d_in[5];  // (D,)
    const float* ln_g   = (const float*)d_in[6];
    const float* ln_b   = (const float*)d_in[7];
    float* out = (float*)d_out;
    const int nnz = in_sizes[1] / 2;

    float *p_Wtmp, *p_Wf, *p_z0, *p_y;
    cudaGetSymbolAddress((void**)&p_Wtmp, g_Wtmp);
    cudaGetSymbolAddress((void**)&p_Wf,   g_Wf);
    cudaGetSymbolAddress((void**)&p_z0,   g_z0);
    cudaGetSymbolAddress((void**)&p_y,    g_y);
    float* p_bf;
    cudaGetSymbolAddress((void**)&p_bf,   g_bf);

    // 1) mixing vectors (tiny)
    k_mix<<<1, 32>>>(he, nnz);

    // 2) weight folds: Wtmp = W1 @ W2 ; Wf = Wtmp @ comb_w
    {
        dim3 grid(Dc / 64, Dc / 64);
        sgemm<64, 64, 16, 4, 4, 0><<<grid, 256>>>(Dc, Dc, Dc, lin_w, lin_w + Dc * Dc,
                                                  nullptr, p_Wtmp);
    }
    k_bias1<<<Dc / 128, 128>>>(lin_b, lin_w + Dc * Dc);
    {
        dim3 grid(Dc / 64, Dc / 64);
        sgemm<64, 64, 16, 4, 4, 0><<<grid, 256>>>(Dc, Dc, Dc, p_Wtmp, comb_w,
                                                  nullptr, p_Wf);
    }
    k_bias2<<<Dc / 128, 128>>>(comb_w, comb_b);

    // 3) weighted expert reduce: z0 = sum_u w1[u] * x[:,u,:]
    {
        int total = Gc * (Dc / 4);
        k_reduce<<<(total + 255) / 256, 256>>>(x, p_z0);
    }

    // 4) main GEMM with bias + exact GELU epilogue: y = gelu(z0 @ Wf + bf)
    {
        dim3 grid(Dc / 128, Gc / 128);
        sgemm<128, 128, 16, 8, 8, 1><<<grid, 256>>>(Gc, Dc, Dc, p_z0, p_Wf, p_bf, p_y);
    }

    // 5) LayerNorm -> output
    k_ln<<<Gc, 128>>>(p_y, ln_g, ln_b, out);
}

// round 3
// speedup vs baseline: 1.6488x; 1.6488x over previous
#include <cuda_runtime.h>
#include <math.h>

// Problem constants (fixed-shape problem): B=4, L=1024, E=8, D=512, NLAYERS=2
#define Dc 512
#define Gc 4096   // B*L
#define Ec 8
#define MAXEDGE 256

// ---------------- scratch (device globals; no allocations allowed) ----------
__device__ float g_w1[Ec];          // folded expert-mixing weights
__device__ float g_s2;              // scalar bias passthrough factor
__device__ float g_Wtmp[Dc*Dc];     // W1 @ W2
__device__ float g_Wf[Dc*Dc];       // W1 @ W2 @ comb_w
__device__ float g_b1f[Dc];         // s2*(b1 @ W2) + b2
__device__ float g_bf[Dc];          // b1f @ comb_w + comb_b
__device__ float g_z0[Gc*Dc];       // weighted expert reduce
__device__ float g_y[Gc*Dc];        // gelu(z0 @ Wf + bf)

// ---------------- 1) mixing vectors from hyperedge_index (parallel) ---------
__global__ void k_mix(const int* __restrict__ he, int nnz) {
    __shared__ float M2s[Ec][Ec];
    __shared__ float degn[Ec];
    __shared__ float dege[MAXEDGE];
    __shared__ float Dinv[Ec];
    __shared__ float Binv[MAXEDGE];
    const int* node = he;
    const int* edge = he + nnz;
    int t = threadIdx.x;  // 128 threads

    if (t < Ec) degn[t] = 0.f;
    for (int e = t; e < MAXEDGE; e += blockDim.x) dege[e] = 0.f;
    if (t < Ec * Ec) ((float*)M2s)[t] = 0.f;
    __syncthreads();

    for (int i = t; i < nnz; i += blockDim.x) {
        atomicAdd(&degn[node[i]], 1.f);
        atomicAdd(&dege[edge[i]], 1.f);
    }
    __syncthreads();
    if (t < Ec) Dinv[t] = degn[t] > 0.f ? 1.f / degn[t] : 0.f;
    for (int e = t; e < MAXEDGE; e += blockDim.x)
        Binv[e] = dege[e] > 0.f ? 1.f / dege[e] : 0.f;
    __syncthreads();

    // M2[v][u] = Dinv[v] * sum_e H[v,e] H[u,e] Binv[e]  over nnz^2 pair space
    int total = nnz * nnz;
    for (int p = t; p < total; p += blockDim.x) {
        int i = p % nnz, j = p / nnz;
        int ei = edge[i];
        if (ei == edge[j])
            atomicAdd(&M2s[node[j]][node[i]], Dinv[node[j]] * Binv[ei]);
    }
    __syncthreads();

    if (t == 0) {
        float w2[Ec], s2 = 0.f;
        for (int u = 0; u < Ec; u++) {
            float s = 0.f;
            for (int v = 0; v < Ec; v++) s += M2s[v][u];
            w2[u] = s / (float)Ec;
            s2 += w2[u];
        }
        for (int q = 0; q < Ec; q++) {
            float s = 0.f;
            for (int u = 0; u < Ec; u++) s += M2s[u][q] * w2[u];
            g_w1[q] = s;
        }
        g_s2 = s2;
    }
}

// ---------------- 2) bias folds ---------------------------------------------
__global__ void k_bias1(const float* __restrict__ lin_b, const float* __restrict__ W2) {
    int n = blockIdx.x * blockDim.x + threadIdx.x;
    if (n >= Dc) return;
    float s2 = g_s2;
    float acc = 0.f;
#pragma unroll 4
    for (int k = 0; k < Dc; k++) acc += lin_b[k] * W2[k * Dc + n];
    g_b1f[n] = s2 * acc + lin_b[Dc + n];
}

__global__ void k_bias2(const float* __restrict__ comb_w, const float* __restrict__ comb_b) {
    int n = blockIdx.x * blockDim.x + threadIdx.x;
    if (n >= Dc) return;
    float acc = 0.f;
#pragma unroll 4
    for (int k = 0; k < Dc; k++) acc += g_b1f[k] * comb_w[k * Dc + n];
    g_bf[n] = acc + comb_b[n];
}

// ---------------- 3) weighted expert reduce (reads the 64MB input once) -----
__global__ void k_reduce(const float* __restrict__ X, float* __restrict__ Z) {
    int i = blockIdx.x * blockDim.x + threadIdx.x;     // over G * (D/4)
    if (i >= Gc * (Dc / 4)) return;
    int g  = i >> 7;          // / (D/4) = /128
    int d4 = i & 127;
    const float4* xp = reinterpret_cast<const float4*>(X) + (size_t)g * Ec * (Dc / 4) + d4;
    float w[Ec];
#pragma unroll
    for (int u = 0; u < Ec; u++) w[u] = g_w1[u];
    float4 acc = make_float4(0.f, 0.f, 0.f, 0.f);
#pragma unroll
    for (int u = 0; u < Ec; u++) {
        float4 v = xp[(size_t)u * (Dc / 4)];
        acc.x = fmaf(w[u], v.x, acc.x);
        acc.y = fmaf(w[u], v.y, acc.y);
        acc.z = fmaf(w[u], v.z, acc.z);
        acc.w = fmaf(w[u], v.w, acc.w);
    }
    reinterpret_cast<float4*>(Z)[i] = acc;
}

// ---------------- 4) pipelined tiled SGEMM ----------------------------------
// C[MxN] = A[MxK](row-major) * B[KxN](row-major) (+bias) (+exact GELU)
// Global->reg prefetch of next K-tile during compute; double-buffered smem;
// one __syncthreads per K-tile; padded smem for conflict-free access.
template <int BM, int BN, int BK, int TM, int TN, int EPI>
__global__ void __launch_bounds__((BM / TM) * (BN / TN))
sgemm(int M, int N, int K,
      const float* __restrict__ A,
      const float* __restrict__ B,
      const float* __restrict__ bias,
      float* __restrict__ C) {
    constexpr int THREADS = (BM / TM) * (BN / TN);
    constexpr int LDA = BM + 4;
    constexpr int LDB = BN + 4;
    constexpr int NA = BM * BK / 4 / THREADS;   // float4 loads per thread for A
    constexpr int NB = BK * BN / 4 / THREADS;   // float4 loads per thread for B
    __shared__ float As[2][BK][LDA];            // A stored transposed: [k][m]
    __shared__ float Bs[2][BK][LDB];

    const int tid  = threadIdx.x;
    const int brow = blockIdx.y * BM;
    const int bcol = blockIdx.x * BN;
    const int tcol = (tid % (BN / TN)) * TN;
    const int trow = (tid / (BN / TN)) * TM;

    int ar[NA], ac[NA], brr[NB], bcc[NB];
#pragma unroll
    for (int t = 0; t < NA; t++) {
        int f = tid + t * THREADS;
        ar[t] = f / (BK / 4);
        ac[t] = (f % (BK / 4)) * 4;
    }
#pragma unroll
    for (int t = 0; t < NB; t++) {
        int f = tid + t * THREADS;
        brr[t] = f / (BN / 4);
        bcc[t] = (f % (BN / 4)) * 4;
    }

    float acc[TM][TN];
#pragma unroll
    for (int m = 0; m < TM; m++)
#pragma unroll
        for (int n = 0; n < TN; n++) acc[m][n] = 0.f;

    float4 afrag[NA], bfrag[NB];

    auto ldg = [&](int k0) {
#pragma unroll
        for (int t = 0; t < NA; t++)
            afrag[t] = *reinterpret_cast<const float4*>(
                &A[(size_t)(brow + ar[t]) * K + k0 + ac[t]]);
#pragma unroll
        for (int t = 0; t < NB; t++)
            bfrag[t] = *reinterpret_cast<const float4*>(
                &B[(size_t)(k0 + brr[t]) * N + bcol + bcc[t]]);
    };
    auto sts = [&](int buf) {
#pragma unroll
        for (int t = 0; t < NA; t++) {
            As[buf][ac[t] + 0][ar[t]] = afrag[t].x;
            As[buf][ac[t] + 1][ar[t]] = afrag[t].y;
            As[buf][ac[t] + 2][ar[t]] = afrag[t].z;
            As[buf][ac[t] + 3][ar[t]] = afrag[t].w;
        }
#pragma unroll
        for (int t = 0; t < NB; t++)
            *reinterpret_cast<float4*>(&Bs[buf][brr[t]][bcc[t]]) = bfrag[t];
    };

    ldg(0);
    sts(0);
    __syncthreads();

    int buf = 0;
    for (int k0 = 0; k0 < K; k0 += BK) {
        const bool has_next = (k0 + BK) < K;
        if (has_next) ldg(k0 + BK);   // LDGs in flight during compute below
#pragma unroll
        for (int kk = 0; kk < BK; kk++) {
            float ra[TM], rb[TN];
#pragma unroll
            for (int m = 0; m < TM; m += 4)
                *reinterpret_cast<float4*>(&ra[m]) =
                    *reinterpret_cast<const float4*>(&As[buf][kk][trow + m]);
#pragma unroll
            for (int n = 0; n < TN; n += 4)
                *reinterpret_cast<float4*>(&rb[n]) =
                    *reinterpret_cast<const float4*>(&Bs[buf][kk][tcol + n]);
#pragma unroll
            for (int m = 0; m < TM; m++)
#pragma unroll
                for (int n = 0; n < TN; n++)
                    acc[m][n] = fmaf(ra[m], rb[n], acc[m][n]);
        }
        if (has_next) {
            sts(buf ^ 1);
            __syncthreads();
            buf ^= 1;
        }
    }

#pragma unroll
    for (int m = 0; m < TM; m++) {
#pragma unroll
        for (int n = 0; n < TN; n += 4) {
            float4 v;
            float* pv = reinterpret_cast<float*>(&v);
#pragma unroll
            for (int q = 0; q < 4; q++) {
                float x = acc[m][n + q];
                if (bias) x += bias[bcol + tcol + n + q];
                if (EPI == 1)  // exact GELU (erf form)
                    x = 0.5f * x * (1.f + erff(x * 0.70710678118654752f));
                pv[q] = x;
            }
            *reinterpret_cast<float4*>(
                &C[(size_t)(brow + trow + m) * N + bcol + tcol + n]) = v;
        }
    }
}

// ---------------- 5) LayerNorm over D=512 (1 block / row) -------------------
__global__ void k_ln(const float* __restrict__ Y, const float* __restrict__ gam,
                     const float* __restrict__ bet, float* __restrict__ out) {
    int row = blockIdx.x;
    const float* y = Y + (size_t)row * Dc;
    int t = threadIdx.x;  // 128 threads
    float v[4];
    float s = 0.f;
#pragma unroll
    for (int i = 0; i < 4; i++) { v[i] = y[t + i * 128]; s += v[i]; }
    __shared__ float red[4];
#pragma unroll
    for (int o = 16; o; o >>= 1) s += __shfl_xor_sync(0xffffffffu, s, o);
    if ((t & 31) == 0) red[t >> 5] = s;
    __syncthreads();
    float mu = (red[0] + red[1] + red[2] + red[3]) * (1.f / Dc);
    __syncthreads();
    float d2 = 0.f;
#pragma unroll
    for (int i = 0; i < 4; i++) { float d = v[i] - mu; d2 += d * d; }
#pragma unroll
    for (int o = 16; o; o >>= 1) d2 += __shfl_xor_sync(0xffffffffu, d2, o);
    if ((t & 31) == 0) red[t >> 5] = d2;
    __syncthreads();
    float var = (red[0] + red[1] + red[2] + red[3]) * (1.f / Dc);
    float rs = rsqrtf(var + 1e-5f);
#pragma unroll
    for (int i = 0; i < 4; i++) {
        int c = t + i * 128;
        out[(size_t)row * Dc + c] = (v[i] - mu) * rs * gam[c] + bet[c];
    }
}

// ---------------- launch -----------------------------------------------------
extern "C" void kernel_launch(void* const* d_in, const int* in_sizes, int n_in,
                              void* d_out, int out_size) {
    const float* x      = (const float*)d_in[0];  // (B,L,E,D)
    const int*   he     = (const int*)  d_in[1];  // (2, nnz)
    const float* lin_w  = (const float*)d_in[2];  // (2, D, D)
    const float* lin_b  = (const float*)d_in[3];  // (2, D)
    const float* comb_w = (const float*)d_in[4];  // (D, D)
    const float* comb_b = (const float*)d_in[5];  // (D,)
    const float* ln_g   = (const float*)d_in[6];
    const float* ln_b   = (const float*)d_in[7];
    float* out = (float*)d_out;
    const int nnz = in_sizes[1] / 2;

    float *p_Wtmp, *p_Wf, *p_z0, *p_y, *p_bf;
    cudaGetSymbolAddress((void**)&p_Wtmp, g_Wtmp);
    cudaGetSymbolAddress((void**)&p_Wf,   g_Wf);
    cudaGetSymbolAddress((void**)&p_z0,   g_z0);
    cudaGetSymbolAddress((void**)&p_y,    g_y);
    cudaGetSymbolAddress((void**)&p_bf,   g_bf);

    // 1) mixing vectors (tiny, parallel)
    k_mix<<<1, 128>>>(he, nnz);

    // 3) weighted expert reduce (independent of folds; launch early)
    {
        int total = Gc * (Dc / 4);
        k_reduce<<<(total + 255) / 256, 256>>>(x, p_z0);
    }

    // 2) weight folds: Wtmp = W1 @ W2 ; Wf = Wtmp @ comb_w
    {
        dim3 grid(Dc / 64, Dc / 64);
        sgemm<64, 64, 16, 4, 4, 0><<<grid, 256>>>(Dc, Dc, Dc, lin_w, lin_w + Dc * Dc,
                                                  nullptr, p_Wtmp);
    }
    k_bias1<<<Dc / 128, 128>>>(lin_b, lin_w + Dc * Dc);
    {
        dim3 grid(Dc / 64, Dc / 64);
        sgemm<64, 64, 16, 4, 4, 0><<<grid, 256>>>(Dc, Dc, Dc, p_Wtmp, comb_w,
                                                  nullptr, p_Wf);
    }
    k_bias2<<<Dc / 128, 128>>>(comb_w, comb_b);

    // 4) main GEMM with bias + exact GELU: y = gelu(z0 @ Wf + bf)
    {
        dim3 grid(Dc / 64, Gc / 128);   // 8 x 32 = 256 blocks
        sgemm<128, 64, 16, 8, 4, 1><<<grid, 256>>>(Gc, Dc, Dc, p_z0, p_Wf, p_bf, p_y);
    }

    // 5) LayerNorm -> output
    k_ln<<<Gc, 128>>>(p_y, ln_g, ln_b, out);
}

// round 5
// speedup vs baseline: 2.3104x; 1.4013x over previous
#include <cuda_runtime.h>
#include <math.h>

// Problem constants (fixed-shape problem): B=4, L=1024, E=8, D=512, NLAYERS=2
#define Dc 512
#define Gc 4096   // B*L
#define Ec 8
#define MAXEDGE 256

// ---------------- scratch (device globals; no allocations allowed) ----------
__device__ float g_w1[Ec];          // folded expert-mixing weights
__device__ float g_s2;              // scalar bias passthrough factor
__device__ float g_Wtmp[Dc*Dc];     // W1 @ W2
__device__ float g_Wf[Dc*Dc];       // W1 @ W2 @ comb_w
__device__ float g_b1f[Dc];         // s2*(b1 @ W2) + b2
__device__ float g_bf[Dc];          // b1f @ comb_w + comb_b
__device__ float g_part[8 * Dc];    // split-K GEMV partials
__device__ float g_z0[Gc*Dc];       // weighted expert reduce
__device__ float g_y[Gc*Dc];        // gelu(z0 @ Wf + bf)

// ---------------- f32x2 packed helpers (Blackwell FFMA2) --------------------
__device__ __forceinline__ unsigned long long bcast2(float x) {
    unsigned long long r;
    asm("mov.b64 %0, {%1, %1};" : "=l"(r) : "f"(x));
    return r;
}
__device__ __forceinline__ void fma2(unsigned long long& d,
                                     unsigned long long a, unsigned long long b) {
    asm("fma.rn.f32x2 %0, %1, %2, %0;" : "+l"(d) : "l"(a), "l"(b));
}
__device__ __forceinline__ float2 unpack2(unsigned long long p) {
    float2 v;
    asm("mov.b64 {%0, %1}, %2;" : "=f"(v.x), "=f"(v.y) : "l"(p));
    return v;
}

// ---------------- 1) mixing vectors from hyperedge_index (parallel) ---------
__global__ void k_mix(const int* __restrict__ he, int nnz) {
    __shared__ float M2s[Ec][Ec];
    __shared__ float degn[Ec];
    __shared__ float dege[MAXEDGE];
    __shared__ float Dinv[Ec];
    __shared__ float Binv[MAXEDGE];
    const int* node = he;
    const int* edge = he + nnz;
    int t = threadIdx.x;  // 128 threads

    if (t < Ec) degn[t] = 0.f;
    for (int e = t; e < MAXEDGE; e += blockDim.x) dege[e] = 0.f;
    if (t < Ec * Ec) ((float*)M2s)[t] = 0.f;
    __syncthreads();

    for (int i = t; i < nnz; i += blockDim.x) {
        atomicAdd(&degn[node[i]], 1.f);
        atomicAdd(&dege[edge[i]], 1.f);
    }
    __syncthreads();
    if (t < Ec) Dinv[t] = degn[t] > 0.f ? 1.f / degn[t] : 0.f;
    for (int e = t; e < MAXEDGE; e += blockDim.x)
        Binv[e] = dege[e] > 0.f ? 1.f / dege[e] : 0.f;
    __syncthreads();

    int total = nnz * nnz;
    for (int p = t; p < total; p += blockDim.x) {
        int i = p % nnz, j = p / nnz;
        int ei = edge[i];
        if (ei == edge[j])
            atomicAdd(&M2s[node[j]][node[i]], Dinv[node[j]] * Binv[ei]);
    }
    __syncthreads();

    if (t == 0) {
        float w2[Ec], s2 = 0.f;
        for (int u = 0; u < Ec; u++) {
            float s = 0.f;
            for (int v = 0; v < Ec; v++) s += M2s[v][u];
            w2[u] = s / (float)Ec;
            s2 += w2[u];
        }
        for (int q = 0; q < Ec; q++) {
            float s = 0.f;
            for (int u = 0; u < Ec; u++) s += M2s[u][q] * w2[u];
            g_w1[q] = s;
        }
        g_s2 = s2;
    }
}

// ---------------- 2) bias folds: split-K GEMV -------------------------------
// part[ky*Dc + n] = sum_{k in [ky*64, ky*64+64)} v[k] * W[k*Dc + n]
__global__ void k_gemv_part(const float* __restrict__ v, const float* __restrict__ W,
                            float* __restrict__ part) {
    int n  = blockIdx.x * 128 + threadIdx.x;
    int k0 = blockIdx.y * 64;
    float acc = 0.f;
#pragma unroll 8
    for (int k = 0; k < 64; k++)
        acc = fmaf(v[k0 + k], W[(size_t)(k0 + k) * Dc + n], acc);
    part[blockIdx.y * Dc + n] = acc;
}

// b1f[n] = s2 * sum_j part[j*Dc+n] + b2[n]      (b2 = lin_b row 1)
__global__ void k_bias1_comb(const float* __restrict__ lin_b) {
    int n = blockIdx.x * blockDim.x + threadIdx.x;
    if (n >= Dc) return;
    float s = 0.f;
#pragma unroll
    for (int j = 0; j < 8; j++) s += g_part[j * Dc + n];
    g_b1f[n] = g_s2 * s + lin_b[Dc + n];
}

// bf[n] = sum_j part[j*Dc+n] + comb_b[n]
__global__ void k_bias2_comb(const float* __restrict__ comb_b) {
    int n = blockIdx.x * blockDim.x + threadIdx.x;
    if (n >= Dc) return;
    float s = 0.f;
#pragma unroll
    for (int j = 0; j < 8; j++) s += g_part[j * Dc + n];
    g_bf[n] = s + comb_b[n];
}

// ---------------- 3) weighted expert reduce (reads the 64MB input once) -----
__global__ void k_reduce(const float* __restrict__ X, float* __restrict__ Z) {
    int i = blockIdx.x * blockDim.x + threadIdx.x;     // over G * (D/4)
    if (i >= Gc * (Dc / 4)) return;
    int g  = i >> 7;          // / (D/4) = /128
    int d4 = i & 127;
    const float4* xp = reinterpret_cast<const float4*>(X) + (size_t)g * Ec * (Dc / 4) + d4;
    float w[Ec];
#pragma unroll
    for (int u = 0; u < Ec; u++) w[u] = g_w1[u];
    float4 acc = make_float4(0.f, 0.f, 0.f, 0.f);
#pragma unroll
    for (int u = 0; u < Ec; u++) {
        float4 v = xp[(size_t)u * (Dc / 4)];
        acc.x = fmaf(w[u], v.x, acc.x);
        acc.y = fmaf(w[u], v.y, acc.y);
        acc.z = fmaf(w[u], v.z, acc.z);
        acc.w = fmaf(w[u], v.w, acc.w);
    }
    reinterpret_cast<float4*>(Z)[i] = acc;
}

// ---------------- 4) pipelined tiled SGEMM with f32x2 packed FMA ------------
// C[MxN] = A[MxK](row-major) * B[KxN](row-major) (+bias) (+exact GELU)
// Accumulators paired over m (FFMA2); A fragments loaded as 64-bit LDS from
// the transposed smem tile; double-buffered smem; one sync per K-tile.
template <int BM, int BN, int BK, int TM, int TN, int EPI>
__global__ void __launch_bounds__((BM / TM) * (BN / TN))
sgemm(int M, int N, int K,
      const float* __restrict__ A,
      const float* __restrict__ B,
      const float* __restrict__ bias,
      float* __restrict__ C) {
    static_assert(TM % 2 == 0, "TM must be even for f32x2 pairing");
    constexpr int THREADS = (BM / TM) * (BN / TN);
    constexpr int LDA = BM + 4;
    constexpr int LDB = BN + 4;
    constexpr int NA = BM * BK / 4 / THREADS;   // float4 loads per thread for A
    constexpr int NB = BK * BN / 4 / THREADS;   // float4 loads per thread for B
    __shared__ __align__(16) float As[2][BK][LDA];   // A transposed: [k][m]
    __shared__ __align__(16) float Bs[2][BK][LDB];

    const int tid  = threadIdx.x;
    const int brow = blockIdx.y * BM;
    const int bcol = blockIdx.x * BN;
    const int tcol = (tid % (BN / TN)) * TN;
    const int trow = (tid / (BN / TN)) * TM;    // multiple of TM (even) -> 8B aligned

    int ar[NA], ac[NA], brr[NB], bcc[NB];
#pragma unroll
    for (int t = 0; t < NA; t++) {
        int f = tid + t * THREADS;
        ar[t] = f / (BK / 4);
        ac[t] = (f % (BK / 4)) * 4;
    }
#pragma unroll
    for (int t = 0; t < NB; t++) {
        int f = tid + t * THREADS;
        brr[t] = f / (BN / 4);
        bcc[t] = (f % (BN / 4)) * 4;
    }

    unsigned long long accp[TM / 2][TN];   // each holds (row 2m, row 2m+1)
#pragma unroll
    for (int m = 0; m < TM / 2; m++)
#pragma unroll
        for (int n = 0; n < TN; n++) accp[m][n] = 0ull;

    float4 afrag[NA], bfrag[NB];

    auto ldg = [&](int k0) {
#pragma unroll
        for (int t = 0; t < NA; t++)
            afrag[t] = *reinterpret_cast<const float4*>(
                &A[(size_t)(brow + ar[t]) * K + k0 + ac[t]]);
#pragma unroll
        for (int t = 0; t < NB; t++)
            bfrag[t] = *reinterpret_cast<const float4*>(
                &B[(size_t)(k0 + brr[t]) * N + bcol + bcc[t]]);
    };
    auto sts = [&](int buf) {
#pragma unroll
        for (int t = 0; t < NA; t++) {
            As[buf][ac[t] + 0][ar[t]] = afrag[t].x;
            As[buf][ac[t] + 1][ar[t]] = afrag[t].y;
            As[buf][ac[t] + 2][ar[t]] = afrag[t].z;
            As[buf][ac[t] + 3][ar[t]] = afrag[t].w;
        }
#pragma unroll
        for (int t = 0; t < NB; t++)
            *reinterpret_cast<float4*>(&Bs[buf][brr[t]][bcc[t]]) = bfrag[t];
    };

    ldg(0);
    sts(0);
    __syncthreads();

    int buf = 0;
    for (int k0 = 0; k0 < K; k0 += BK) {
        const bool has_next = (k0 + BK) < K;
        if (has_next) ldg(k0 + BK);   // LDGs in flight during compute below
#pragma unroll
        for (int kk = 0; kk < BK; kk++) {
            unsigned long long rap[TM / 2];
            const unsigned long long* ap =
                reinterpret_cast<const unsigned long long*>(&As[buf][kk][trow]);
#pragma unroll
            for (int m = 0; m < TM / 2; m++) rap[m] = ap[m];
            float rb[TN];
#pragma unroll
            for (int n = 0; n < TN; n += 4)
                *reinterpret_cast<float4*>(&rb[n]) =
                    *reinterpret_cast<const float4*>(&Bs[buf][kk][tcol + n]);
            unsigned long long rbb[TN];
#pragma unroll
            for (int n = 0; n < TN; n++) rbb[n] = bcast2(rb[n]);
#pragma unroll
            for (int m = 0; m < TM / 2; m++)
#pragma unroll
                for (int n = 0; n < TN; n++) fma2(accp[m][n], rap[m], rbb[n]);
        }
        if (has_next) {
            sts(buf ^ 1);
            __syncthreads();
            buf ^= 1;
        }
    }

    // unpack pairs -> vals[m][n]
    float vals[TM][TN];
#pragma unroll
    for (int m = 0; m < TM / 2; m++)
#pragma unroll
        for (int n = 0; n < TN; n++) {
            float2 v = unpack2(accp[m][n]);
            vals[2 * m + 0][n] = v.x;
            vals[2 * m + 1][n] = v.y;
        }

#pragma unroll
    for (int m = 0; m < TM; m++) {
#pragma unroll
        for (int n = 0; n < TN; n += 4) {
            float4 v;
            float* pv = reinterpret_cast<float*>(&v);
#pragma unroll
            for (int q = 0; q < 4; q++) {
                float x = vals[m][n + q];
                if (bias) x += bias[bcol + tcol + n + q];
                if (EPI == 1)  // exact GELU (erf form)
                    x = 0.5f * x * (1.f + erff(x * 0.70710678118654752f));
                pv[q] = x;
            }
            *reinterpret_cast<float4*>(
                &C[(size_t)(brow + trow + m) * N + bcol + tcol + n]) = v;
        }
    }
}

// ---------------- 5) LayerNorm over D=512 (1 block / row) -------------------
__global__ void k_ln(const float* __restrict__ Y, const float* __restrict__ gam,
                     const float* __restrict__ bet, float* __restrict__ out) {
    int row = blockIdx.x;
    const float* y = Y + (size_t)row * Dc;
    int t = threadIdx.x;  // 128 threads
    float v[4];
    float s = 0.f;
#pragma unroll
    for (int i = 0; i < 4; i++) { v[i] = y[t + i * 128]; s += v[i]; }
    __shared__ float red[4];
#pragma unroll
    for (int o = 16; o; o >>= 1) s += __shfl_xor_sync(0xffffffffu, s, o);
    if ((t & 31) == 0) red[t >> 5] = s;
    __syncthreads();
    float mu = (red[0] + red[1] + red[2] + red[3]) * (1.f / Dc);
    __syncthreads();
    float d2 = 0.f;
#pragma unroll
    for (int i = 0; i < 4; i++) { float d = v[i] - mu; d2 += d * d; }
#pragma unroll
    for (int o = 16; o; o >>= 1) d2 += __shfl_xor_sync(0xffffffffu, d2, o);
    if ((t & 31) == 0) red[t >> 5] = d2;
    __syncthreads();
    float var = (red[0] + red[1] + red[2] + red[3]) * (1.f / Dc);
    float rs = rsqrtf(var + 1e-5f);
#pragma unroll
    for (int i = 0; i < 4; i++) {
        int c = t + i * 128;
        out[(size_t)row * Dc + c] = (v[i] - mu) * rs * gam[c] + bet[c];
    }
}

// ---------------- launch -----------------------------------------------------
extern "C" void kernel_launch(void* const* d_in, const int* in_sizes, int n_in,
                              void* d_out, int out_size) {
    const float* x      = (const float*)d_in[0];  // (B,L,E,D)
    const int*   he     = (const int*)  d_in[1];  // (2, nnz)
    const float* lin_w  = (const float*)d_in[2];  // (2, D, D)
    const float* lin_b  = (const float*)d_in[3];  // (2, D)
    const float* comb_w = (const float*)d_in[4];  // (D, D)
    const float* comb_b = (const float*)d_in[5];  // (D,)
    const float* ln_g   = (const float*)d_in[6];
    const float* ln_b   = (const float*)d_in[7];
    float* out = (float*)d_out;
    const int nnz = in_sizes[1] / 2;

    float *p_Wtmp, *p_Wf, *p_z0, *p_y, *p_bf, *p_b1f, *p_part;
    cudaGetSymbolAddress((void**)&p_Wtmp, g_Wtmp);
    cudaGetSymbolAddress((void**)&p_Wf,   g_Wf);
    cudaGetSymbolAddress((void**)&p_z0,   g_z0);
    cudaGetSymbolAddress((void**)&p_y,    g_y);
    cudaGetSymbolAddress((void**)&p_bf,   g_bf);
    cudaGetSymbolAddress((void**)&p_b1f,  g_b1f);
    cudaGetSymbolAddress((void**)&p_part, g_part);

    // 1) mixing vectors (tiny, parallel)
    k_mix<<<1, 128>>>(he, nnz);

    // 3) weighted expert reduce (independent of folds; launch early)
    {
        int total = Gc * (Dc / 4);
        k_reduce<<<(total + 255) / 256, 256>>>(x, p_z0);
    }

    // 2) weight folds: Wtmp = W1 @ W2 ; Wf = Wtmp @ comb_w
    {
        dim3 grid(Dc / 64, Dc / 64);
        sgemm<64, 64, 16, 4, 4, 0><<<grid, 256>>>(Dc, Dc, Dc, lin_w, lin_w + Dc * Dc,
                                                  nullptr, p_Wtmp);
    }
    // bias1: b1f = s2*(b1 @ W2) + b2   (split-K GEMV: 32 blocks + combine)
    {
        dim3 grid(Dc / 128, 8);
        k_gemv_part<<<grid, 128>>>(lin_b, lin_w + Dc * Dc, p_part);
        k_bias1_comb<<<Dc / 128, 128>>>(lin_b);
    }
    {
        dim3 grid(Dc / 64, Dc / 64);
        sgemm<64, 64, 16, 4, 4, 0><<<grid, 256>>>(Dc, Dc, Dc, p_Wtmp, comb_w,
                                                  nullptr, p_Wf);
    }
    // bias2: bf = b1f @ comb_w + comb_b
    {
        dim3 grid(Dc / 128, 8);
        k_gemv_part<<<grid, 128>>>(p_b1f, comb_w, p_part);
        k_bias2_comb<<<Dc / 128, 128>>>(comb_b);
    }

    // 4) main GEMM with bias + exact GELU: y = gelu(z0 @ Wf + bf)
    {
        dim3 grid(Dc / 64, Gc / 128);   // 8 x 32 = 256 blocks
        sgemm<128, 64, 16, 8, 4, 1><<<grid, 256>>>(Gc, Dc, Dc, p_z0, p_Wf, p_bf, p_y);
    }

    // 5) LayerNorm -> output
    k_ln<<<Gc, 128>>>(p_y, ln_g, ln_b, out);
}

// round 7
// speedup vs baseline: 2.3849x; 1.0322x over previous
#include <cuda_runtime.h>
#include <math.h>

// Problem constants (fixed-shape problem): B=4, L=1024, E=8, D=512, NLAYERS=2
#define Dc 512
#define Gc 4096   // B*L
#define Ec 8
#define MAXEDGE 256

// ---------------- scratch (device globals; no allocations allowed) ----------
__device__ float g_w1[Ec];          // folded expert-mixing weights
__device__ float g_s2;              // scalar bias passthrough factor
__device__ __align__(16) float g_Wtmp[Dc*Dc];  // W1 @ W2
__device__ __align__(16) float g_Wf[Dc*Dc];    // W1 @ W2 @ comb_w
__device__ __align__(16) float g_b1f[Dc];      // s2*(b1 @ W2) + b2
__device__ __align__(16) float g_bf[Dc];       // b1f @ comb_w + comb_b
__device__ __align__(16) float g_z0[Gc*Dc];    // weighted expert reduce
__device__ __align__(16) float g_y[Gc*Dc];     // gelu(z0 @ Wf + bf)

// ---------------- f32x2 packed helpers (Blackwell FFMA2) --------------------
__device__ __forceinline__ unsigned long long bcast2(float x) {
    unsigned long long r;
    asm("mov.b64 %0, {%1, %1};" : "=l"(r) : "f"(x));
    return r;
}
__device__ __forceinline__ void fma2(unsigned long long& d,
                                     unsigned long long a, unsigned long long b) {
    asm("fma.rn.f32x2 %0, %1, %2, %0;" : "+l"(d) : "l"(a), "l"(b));
}
__device__ __forceinline__ float2 unpack2(unsigned long long p) {
    float2 v;
    asm("mov.b64 {%0, %1}, %2;" : "=f"(v.x), "=f"(v.y) : "l"(p));
    return v;
}

// ---------------- 1) mixing vectors from hyperedge_index (parallel) ---------
__global__ void k_mix(const int* __restrict__ he, int nnz) {
    __shared__ float M2s[Ec][Ec];
    __shared__ float degn[Ec];
    __shared__ float dege[MAXEDGE];
    __shared__ float Dinv[Ec];
    __shared__ float Binv[MAXEDGE];
    const int* node = he;
    const int* edge = he + nnz;
    int t = threadIdx.x;  // 128 threads

    if (t < Ec) degn[t] = 0.f;
    for (int e = t; e < MAXEDGE; e += blockDim.x) dege[e] = 0.f;
    if (t < Ec * Ec) ((float*)M2s)[t] = 0.f;
    __syncthreads();

    for (int i = t; i < nnz; i += blockDim.x) {
        atomicAdd(&degn[node[i]], 1.f);
        atomicAdd(&dege[edge[i]], 1.f);
    }
    __syncthreads();
    if (t < Ec) Dinv[t] = degn[t] > 0.f ? 1.f / degn[t] : 0.f;
    for (int e = t; e < MAXEDGE; e += blockDim.x)
        Binv[e] = dege[e] > 0.f ? 1.f / dege[e] : 0.f;
    __syncthreads();

    int total = nnz * nnz;
    for (int p = t; p < total; p += blockDim.x) {
        int i = p % nnz, j = p / nnz;
        int ei = edge[i];
        if (ei == edge[j])
            atomicAdd(&M2s[node[j]][node[i]], Dinv[node[j]] * Binv[ei]);
    }
    __syncthreads();

    if (t == 0) {
        float w2[Ec], s2 = 0.f;
        for (int u = 0; u < Ec; u++) {
            float s = 0.f;
            for (int v = 0; v < Ec; v++) s += M2s[v][u];
            w2[u] = s / (float)Ec;
            s2 += w2[u];
        }
        for (int q = 0; q < Ec; q++) {
            float s = 0.f;
            for (int u = 0; u < Ec; u++) s += M2s[u][q] * w2[u];
            g_w1[q] = s;
        }
        g_s2 = s2;
    }
}

// ---------------- 2) weighted expert reduce (reads the 64MB input once) -----
__global__ void k_reduce(const float* __restrict__ X, float* __restrict__ Z) {
    int i = blockIdx.x * blockDim.x + threadIdx.x;     // over G * (D/4)
    if (i >= Gc * (Dc / 4)) return;
    int g  = i >> 7;          // / (D/4) = /128
    int d4 = i & 127;
    const float4* xp = reinterpret_cast<const float4*>(X) + (size_t)g * Ec * (Dc / 4) + d4;
    float w[Ec];
#pragma unroll
    for (int u = 0; u < Ec; u++) w[u] = g_w1[u];
    float4 acc = make_float4(0.f, 0.f, 0.f, 0.f);
#pragma unroll
    for (int u = 0; u < Ec; u++) {
        float4 v = xp[(size_t)u * (Dc / 4)];
        acc.x = fmaf(w[u], v.x, acc.x);
        acc.y = fmaf(w[u], v.y, acc.y);
        acc.z = fmaf(w[u], v.z, acc.z);
        acc.w = fmaf(w[u], v.w, acc.w);
    }
    reinterpret_cast<float4*>(Z)[i] = acc;
}

// ---------------- 3) pipelined tiled SGEMM (FFMA2) with optional fusions ----
// C[MxN] = A[MxK](row-major) * B[KxN](row-major) (+bias) (+exact GELU)
// FB=1: additionally computes bias_out[n] = (use_s2? g_s2:1)*(vsrc @ B)[n]
//       + extra_b[n] in the blockIdx.y==0 blocks (reuses smem B tiles).
template <int BM, int BN, int BK, int TM, int TN, int EPI, int FB>
__global__ void __launch_bounds__((BM / TM) * (BN / TN))
sgemm(int M, int N, int K,
      const float* __restrict__ A,
      const float* __restrict__ B,
      const float* __restrict__ bias,
      float* __restrict__ C,
      const float* __restrict__ vsrc,
      const float* __restrict__ extra_b,
      float* __restrict__ bias_out,
      int use_s2) {
    static_assert(TM % 2 == 0, "TM must be even for f32x2 pairing");
    constexpr int THREADS = (BM / TM) * (BN / TN);
    constexpr int LDA = BM + 4;
    constexpr int LDB = BN + 4;
    constexpr int NA = BM * BK / 4 / THREADS;   // float4 loads per thread for A
    constexpr int NB = BK * BN / 4 / THREADS;   // float4 loads per thread for B
    __shared__ __align__(16) float As[2][BK][LDA];   // A transposed: [k][m]
    __shared__ __align__(16) float Bs[2][BK][LDB];
    __shared__ float vsm[FB ? 512 : 1];

    const int tid  = threadIdx.x;
    const int brow = blockIdx.y * BM;
    const int bcol = blockIdx.x * BN;
    const int tcol = (tid % (BN / TN)) * TN;
    const int trow = (tid / (BN / TN)) * TM;

    int ar[NA], ac[NA], brr[NB], bcc[NB];
#pragma unroll
    for (int t = 0; t < NA; t++) {
        int f = tid + t * THREADS;
        ar[t] = f / (BK / 4);
        ac[t] = (f % (BK / 4)) * 4;
    }
#pragma unroll
    for (int t = 0; t < NB; t++) {
        int f = tid + t * THREADS;
        brr[t] = f / (BN / 4);
        bcc[t] = (f % (BN / 4)) * 4;
    }

    unsigned long long accp[TM / 2][TN];   // each holds (row 2m, row 2m+1)
#pragma unroll
    for (int m = 0; m < TM / 2; m++)
#pragma unroll
        for (int n = 0; n < TN; n++) accp[m][n] = 0ull;

    float4 afrag[NA], bfrag[NB];

    auto ldg = [&](int k0) {
#pragma unroll
        for (int t = 0; t < NA; t++)
            afrag[t] = *reinterpret_cast<const float4*>(
                &A[(size_t)(brow + ar[t]) * K + k0 + ac[t]]);
#pragma unroll
        for (int t = 0; t < NB; t++)
            bfrag[t] = *reinterpret_cast<const float4*>(
                &B[(size_t)(k0 + brr[t]) * N + bcol + bcc[t]]);
    };
    auto sts = [&](int buf) {
#pragma unroll
        for (int t = 0; t < NA; t++) {
            As[buf][ac[t] + 0][ar[t]] = afrag[t].x;
            As[buf][ac[t] + 1][ar[t]] = afrag[t].y;
            As[buf][ac[t] + 2][ar[t]] = afrag[t].z;
            As[buf][ac[t] + 3][ar[t]] = afrag[t].w;
        }
#pragma unroll
        for (int t = 0; t < NB; t++)
            *reinterpret_cast<float4*>(&Bs[buf][brr[t]][bcc[t]]) = bfrag[t];
    };

    if (FB) {
        for (int i = tid; i < K; i += THREADS) vsm[i] = vsrc[i];
    }
    const bool bth = FB && (blockIdx.y == 0) && (tid < BN);
    float bacc = 0.f;

    ldg(0);
    sts(0);
    __syncthreads();

    int buf = 0;
    for (int k0 = 0; k0 < K; k0 += BK) {
        const bool has_next = (k0 + BK) < K;
        if (has_next) ldg(k0 + BK);   // LDGs in flight during compute below
#pragma unroll
        for (int kk = 0; kk < BK; kk++) {
            unsigned long long rap[TM / 2];
            const unsigned long long* ap =
                reinterpret_cast<const unsigned long long*>(&As[buf][kk][trow]);
#pragma unroll
            for (int m = 0; m < TM / 2; m++) rap[m] = ap[m];
            float rb[TN];
#pragma unroll
            for (int n = 0; n < TN; n += 4)
                *reinterpret_cast<float4*>(&rb[n]) =
                    *reinterpret_cast<const float4*>(&Bs[buf][kk][tcol + n]);
            unsigned long long rbb[TN];
#pragma unroll
            for (int n = 0; n < TN; n++) rbb[n] = bcast2(rb[n]);
#pragma unroll
            for (int m = 0; m < TM / 2; m++)
#pragma unroll
                for (int n = 0; n < TN; n++) fma2(accp[m][n], rap[m], rbb[n]);
        }
        if (bth) {   // fused GEMV: reuse the resident Bs[buf] tile
#pragma unroll 4
            for (int kk = 0; kk < BK; kk++)
                bacc = fmaf(vsm[k0 + kk], Bs[buf][kk][tid], bacc);
        }
        if (has_next) {
            sts(buf ^ 1);
            __syncthreads();
            buf ^= 1;
        }
    }

    if (bth) {
        float r = use_s2 ? (g_s2 * bacc) : bacc;
        bias_out[bcol + tid] = r + extra_b[bcol + tid];
    }

    // unpack pairs -> vals[m][n]
    float vals[TM][TN];
#pragma unroll
    for (int m = 0; m < TM / 2; m++)
#pragma unroll
        for (int n = 0; n < TN; n++) {
            float2 v = unpack2(accp[m][n]);
            vals[2 * m + 0][n] = v.x;
            vals[2 * m + 1][n] = v.y;
        }

#pragma unroll
    for (int m = 0; m < TM; m++) {
#pragma unroll
        for (int n = 0; n < TN; n += 4) {
            float4 v;
            float* pv = reinterpret_cast<float*>(&v);
#pragma unroll
            for (int q = 0; q < 4; q++) {
                float x = vals[m][n + q];
                if (bias) x += bias[bcol + tcol + n + q];
                if (EPI == 1)  // exact GELU (erf form)
                    x = 0.5f * x * (1.f + erff(x * 0.70710678118654752f));
                pv[q] = x;
            }
            *reinterpret_cast<float4*>(
                &C[(size_t)(brow + trow + m) * N + bcol + tcol + n]) = v;
        }
    }
}

// ---------------- 4) LayerNorm over D=512 (1 block / row) -------------------
__global__ void k_ln(const float* __restrict__ Y, const float* __restrict__ gam,
                     const float* __restrict__ bet, float* __restrict__ out) {
    int row = blockIdx.x;
    const float* y = Y + (size_t)row * Dc;
    int t = threadIdx.x;  // 128 threads
    float v[4];
    float s = 0.f;
#pragma unroll
    for (int i = 0; i < 4; i++) { v[i] = y[t + i * 128]; s += v[i]; }
    __shared__ float red[4];
#pragma unroll
    for (int o = 16; o; o >>= 1) s += __shfl_xor_sync(0xffffffffu, s, o);
    if ((t & 31) == 0) red[t >> 5] = s;
    __syncthreads();
    float mu = (red[0] + red[1] + red[2] + red[3]) * (1.f / Dc);
    __syncthreads();
    float d2 = 0.f;
#pragma unroll
    for (int i = 0; i < 4; i++) { float d = v[i] - mu; d2 += d * d; }
#pragma unroll
    for (int o = 16; o; o >>= 1) d2 += __shfl_xor_sync(0xffffffffu, d2, o);
    if ((t & 31) == 0) red[t >> 5] = d2;
    __syncthreads();
    float var = (red[0] + red[1] + red[2] + red[3]) * (1.f / Dc);
    float rs = rsqrtf(var + 1e-5f);
#pragma unroll
    for (int i = 0; i < 4; i++) {
        int c = t + i * 128;
        out[(size_t)row * Dc + c] = (v[i] - mu) * rs * gam[c] + bet[c];
    }
}

// ---------------- launch -----------------------------------------------------
extern "C" void kernel_launch(void* const* d_in, const int* in_sizes, int n_in,
                              void* d_out, int out_size) {
    const float* x      = (const float*)d_in[0];  // (B,L,E,D)
    const int*   he     = (const int*)  d_in[1];  // (2, nnz)
    const float* lin_w  = (const float*)d_in[2];  // (2, D, D)
    const float* lin_b  = (const float*)d_in[3];  // (2, D)
    const float* comb_w = (const float*)d_in[4];  // (D, D)
    const float* comb_b = (const float*)d_in[5];  // (D,)
    const float* ln_g   = (const float*)d_in[6];
    const float* ln_b   = (const float*)d_in[7];
    float* out = (float*)d_out;
    const int nnz = in_sizes[1] / 2;

    float *p_Wtmp, *p_Wf, *p_z0, *p_y, *p_bf, *p_b1f;
    cudaGetSymbolAddress((void**)&p_Wtmp, g_Wtmp);
    cudaGetSymbolAddress((void**)&p_Wf,   g_Wf);
    cudaGetSymbolAddress((void**)&p_z0,   g_z0);
    cudaGetSymbolAddress((void**)&p_y,    g_y);
    cudaGetSymbolAddress((void**)&p_bf,   g_bf);
    cudaGetSymbolAddress((void**)&p_b1f,  g_b1f);

    // 1) mixing vectors (tiny, parallel)
    k_mix<<<1, 128>>>(he, nnz);

    // 2) weighted expert reduce: z0 = sum_u w1[u] * x[:,u,:]
    {
        int total = Gc * (Dc / 4);
        k_reduce<<<(total + 255) / 256, 256>>>(x, p_z0);
    }

    // 3) fold 1: Wtmp = W1 @ W2  (+fused: b1f = s2*(b1 @ W2) + b2)
    {
        dim3 grid(Dc / 64, Dc / 32);   // (8, 16) = 128 blocks
        sgemm<32, 64, 32, 2, 4, 0, 1><<<grid, 256>>>(
            Dc, Dc, Dc, lin_w, lin_w + Dc * Dc, nullptr, p_Wtmp,
            lin_b, lin_b + Dc, p_b1f, 1);
    }
    // 4) fold 2: Wf = Wtmp @ comb_w  (+fused: bf = b1f @ comb_w + comb_b)
    {
        dim3 grid(Dc / 64, Dc / 32);
        sgemm<32, 64, 32, 2, 4, 0, 1><<<grid, 256>>>(
            Dc, Dc, Dc, p_Wtmp, comb_w, nullptr, p_Wf,
            p_b1f, comb_b, p_bf, 0);
    }

    // 5) main GEMM with bias + exact GELU: y = gelu(z0 @ Wf + bf)
    {
        dim3 grid(Dc / 128, Gc / 128);   // (4, 32) = 128 blocks = 1 wave
        sgemm<128, 128, 16, 8, 8, 1, 0><<<grid, 256>>>(
            Gc, Dc, Dc, p_z0, p_Wf, p_bf, p_y,
            nullptr, nullptr, nullptr, 0);
    }

    // 6) LayerNorm -> output
    k_ln<<<Gc, 128>>>(p_y, ln_g, ln_b, out);
}

// round 8
// speedup vs baseline: 2.6274x; 1.1017x over previous
#include <cuda_runtime.h>
#include <math.h>

// Problem constants (fixed-shape problem): B=4, L=1024, E=8, D=512, NLAYERS=2
#define Dc 512
#define Gc 4096   // B*L
#define Ec 8
#define MAXEDGE 256
#define KZ 4      // split-K factor for fold GEMMs
#define KLEN 128  // Dc / KZ

// ---------------- scratch (device globals; no allocations allowed) ----------
__device__ float g_w1[Ec];          // folded expert-mixing weights
__device__ float g_s2;              // scalar bias passthrough factor
__device__ __align__(16) float g_partW[KZ * Dc * Dc];  // split-K W partials (4MB)
__device__ __align__(16) float g_partb[KZ * Dc];       // split-K bias partials
__device__ __align__(16) float g_Wtmp[Dc*Dc];  // W1 @ W2
__device__ __align__(16) float g_Wf[Dc*Dc];    // W1 @ W2 @ comb_w
__device__ __align__(16) float g_b1f[Dc];      // s2*(b1 @ W2) + b2
__device__ __align__(16) float g_bf[Dc];       // b1f @ comb_w + comb_b
__device__ __align__(16) float g_z0[Gc*Dc];    // weighted expert reduce
__device__ __align__(16) float g_y[Gc*Dc];     // gelu(z0 @ Wf + bf)

// ---------------- f32x2 packed helpers (Blackwell FFMA2) --------------------
__device__ __forceinline__ unsigned long long bcast2(float x) {
    unsigned long long r;
    asm("mov.b64 %0, {%1, %1};" : "=l"(r) : "f"(x));
    return r;
}
__device__ __forceinline__ void fma2(unsigned long long& d,
                                     unsigned long long a, unsigned long long b) {
    asm("fma.rn.f32x2 %0, %1, %2, %0;" : "+l"(d) : "l"(a), "l"(b));
}
__device__ __forceinline__ float2 unpack2(unsigned long long p) {
    float2 v;
    asm("mov.b64 {%0, %1}, %2;" : "=f"(v.x), "=f"(v.y) : "l"(p));
    return v;
}

// ---------------- 1) mixing vectors from hyperedge_index (parallel) ---------
__global__ void k_mix(const int* __restrict__ he, int nnz) {
    __shared__ float M2s[Ec][Ec];
    __shared__ float degn[Ec];
    __shared__ float dege[MAXEDGE];
    __shared__ float Dinv[Ec];
    __shared__ float Binv[MAXEDGE];
    const int* node = he;
    const int* edge = he + nnz;
    int t = threadIdx.x;  // 128 threads

    if (t < Ec) degn[t] = 0.f;
    for (int e = t; e < MAXEDGE; e += blockDim.x) dege[e] = 0.f;
    if (t < Ec * Ec) ((float*)M2s)[t] = 0.f;
    __syncthreads();

    for (int i = t; i < nnz; i += blockDim.x) {
        atomicAdd(&degn[node[i]], 1.f);
        atomicAdd(&dege[edge[i]], 1.f);
    }
    __syncthreads();
    if (t < Ec) Dinv[t] = degn[t] > 0.f ? 1.f / degn[t] : 0.f;
    for (int e = t; e < MAXEDGE; e += blockDim.x)
        Binv[e] = dege[e] > 0.f ? 1.f / dege[e] : 0.f;
    __syncthreads();

    int total = nnz * nnz;
    for (int p = t; p < total; p += blockDim.x) {
        int i = p % nnz, j = p / nnz;
        int ei = edge[i];
        if (ei == edge[j])
            atomicAdd(&M2s[node[j]][node[i]], Dinv[node[j]] * Binv[ei]);
    }
    __syncthreads();

    if (t == 0) {
        float w2[Ec], s2 = 0.f;
        for (int u = 0; u < Ec; u++) {
            float s = 0.f;
            for (int v = 0; v < Ec; v++) s += M2s[v][u];
            w2[u] = s / (float)Ec;
            s2 += w2[u];
        }
        for (int q = 0; q < Ec; q++) {
            float s = 0.f;
            for (int u = 0; u < Ec; u++) s += M2s[u][q] * w2[u];
            g_w1[q] = s;
        }
        g_s2 = s2;
    }
}

// ---------------- 2) weighted expert reduce (reads the 64MB input once) -----
__global__ void k_reduce(const float* __restrict__ X, float* __restrict__ Z) {
    int i = blockIdx.x * blockDim.x + threadIdx.x;     // over G * (D/4)
    if (i >= Gc * (Dc / 4)) return;
    int g  = i >> 7;          // / (D/4) = /128
    int d4 = i & 127;
    const float4* xp = reinterpret_cast<const float4*>(X) + (size_t)g * Ec * (Dc / 4) + d4;
    float w[Ec];
#pragma unroll
    for (int u = 0; u < Ec; u++) w[u] = g_w1[u];
    float4 acc = make_float4(0.f, 0.f, 0.f, 0.f);
#pragma unroll
    for (int u = 0; u < Ec; u++) {
        float4 v = xp[(size_t)u * (Dc / 4)];
        acc.x = fmaf(w[u], v.x, acc.x);
        acc.y = fmaf(w[u], v.y, acc.y);
        acc.z = fmaf(w[u], v.z, acc.z);
        acc.w = fmaf(w[u], v.w, acc.w);
    }
    reinterpret_cast<float4*>(Z)[i] = acc;
}

// ---------------- 3) split-K fold GEMM (64x64x128 per block) ----------------
// partW[kz] += A[:, kz*128:+128] @ B[kz*128:+128, :]  (64x64 tile per block)
// Also: partb[kz][n] = sum_k vsrc[kz*128+k] * B[kz*128+k][n] in by==0 blocks.
__global__ void __launch_bounds__(256)
k_fold(const float* __restrict__ A, const float* __restrict__ B,
       const float* __restrict__ vsrc,
       float* __restrict__ partW, float* __restrict__ partb) {
    constexpr int BM = 64, BN = 64, BK = 16, TM = 4, TN = 4, THREADS = 256;
    constexpr int LDA = BM + 4, LDB = BN + 4;
    __shared__ __align__(16) float As[2][BK][LDA];
    __shared__ __align__(16) float Bs[2][BK][LDB];
    __shared__ float vsm[KLEN];

    const int tid   = threadIdx.x;
    const int brow  = blockIdx.y * BM;
    const int bcol  = blockIdx.x * BN;
    const int kz    = blockIdx.z;
    const int kbase = kz * KLEN;
    const int tcol  = (tid % (BN / TN)) * TN;
    const int trow  = (tid / (BN / TN)) * TM;

    // one float4 load per thread for each of A,B per K-tile
    const int ar = tid / (BK / 4);          // 0..63
    const int ac = (tid % (BK / 4)) * 4;    // 0,4,8,12
    const int br = tid / (BN / 4);          // 0..15
    const int bc = (tid % (BN / 4)) * 4;    // 0..60

    for (int i = tid; i < KLEN; i += THREADS) vsm[i] = vsrc[kbase + i];
    const bool bth = (blockIdx.y == 0) && (tid < BN);
    float bacc = 0.f;

    unsigned long long accp[TM / 2][TN];
#pragma unroll
    for (int m = 0; m < TM / 2; m++)
#pragma unroll
        for (int n = 0; n < TN; n++) accp[m][n] = 0ull;

    float4 afrag, bfrag;
    auto ldg = [&](int k0) {
        afrag = *reinterpret_cast<const float4*>(
            &A[(size_t)(brow + ar) * Dc + kbase + k0 + ac]);
        bfrag = *reinterpret_cast<const float4*>(
            &B[(size_t)(kbase + k0 + br) * Dc + bcol + bc]);
    };
    auto sts = [&](int buf) {
        As[buf][ac + 0][ar] = afrag.x;
        As[buf][ac + 1][ar] = afrag.y;
        As[buf][ac + 2][ar] = afrag.z;
        As[buf][ac + 3][ar] = afrag.w;
        *reinterpret_cast<float4*>(&Bs[buf][br][bc]) = bfrag;
    };

    ldg(0);
    sts(0);
    __syncthreads();

    int buf = 0;
    for (int k0 = 0; k0 < KLEN; k0 += BK) {
        const bool has_next = (k0 + BK) < KLEN;
        if (has_next) ldg(k0 + BK);
#pragma unroll
        for (int kk = 0; kk < BK; kk++) {
            unsigned long long rap[TM / 2];
            const unsigned long long* ap =
                reinterpret_cast<const unsigned long long*>(&As[buf][kk][trow]);
#pragma unroll
            for (int m = 0; m < TM / 2; m++) rap[m] = ap[m];
            float rb[TN];
#pragma unroll
            for (int n = 0; n < TN; n += 4)
                *reinterpret_cast<float4*>(&rb[n]) =
                    *reinterpret_cast<const float4*>(&Bs[buf][kk][tcol + n]);
            unsigned long long rbb[TN];
#pragma unroll
            for (int n = 0; n < TN; n++) rbb[n] = bcast2(rb[n]);
#pragma unroll
            for (int m = 0; m < TM / 2; m++)
#pragma unroll
                for (int n = 0; n < TN; n++) fma2(accp[m][n], rap[m], rbb[n]);
        }
        if (bth) {
#pragma unroll 4
            for (int kk = 0; kk < BK; kk++)
                bacc = fmaf(vsm[k0 + kk], Bs[buf][kk][tid], bacc);
        }
        if (has_next) {
            sts(buf ^ 1);
            __syncthreads();
            buf ^= 1;
        }
    }

    if (bth) partb[kz * Dc + bcol + tid] = bacc;

    float* W = partW + (size_t)kz * Dc * Dc;
#pragma unroll
    for (int m = 0; m < TM / 2; m++)
#pragma unroll
        for (int n = 0; n < TN; n++) {
            float2 v = unpack2(accp[m][n]);
            W[(size_t)(brow + trow + 2 * m + 0) * Dc + bcol + tcol + n] = v.x;
            W[(size_t)(brow + trow + 2 * m + 1) * Dc + bcol + tcol + n] = v.y;
        }
}

// ---------------- 4) split-K combine (W + bias, fixed order = deterministic) -
__global__ void k_comb(float* __restrict__ Wout,
                       const float* __restrict__ extra_b,
                       float* __restrict__ bias_out, int use_s2) {
    int i = blockIdx.x * blockDim.x + threadIdx.x;   // over Dc*Dc/4 = 65536
    const float4* p = reinterpret_cast<const float4*>(g_partW);
    constexpr int STRIDE = Dc * Dc / 4;
    float4 a = p[i], b = p[i + STRIDE], c = p[i + 2 * STRIDE], d = p[i + 3 * STRIDE];
    float4 r;
    r.x = ((a.x + b.x) + c.x) + d.x;
    r.y = ((a.y + b.y) + c.y) + d.y;
    r.z = ((a.z + b.z) + c.z) + d.z;
    r.w = ((a.w + b.w) + c.w) + d.w;
    reinterpret_cast<float4*>(Wout)[i] = r;
    if (i < Dc) {
        float s = ((g_partb[i] + g_partb[Dc + i]) + g_partb[2 * Dc + i])
                  + g_partb[3 * Dc + i];
        bias_out[i] = (use_s2 ? (g_s2 * s) : s) + extra_b[i];
    }
}

// ---------------- 5) pipelined tiled SGEMM (FFMA2) --------------------------
// C[MxN] = A[MxK](row-major) * B[KxN](row-major) (+bias) (+exact GELU)
template <int BM, int BN, int BK, int TM, int TN, int EPI>
__global__ void __launch_bounds__((BM / TM) * (BN / TN))
sgemm(int M, int N, int K,
      const float* __restrict__ A,
      const float* __restrict__ B,
      const float* __restrict__ bias,
      float* __restrict__ C) {
    static_assert(TM % 2 == 0, "TM must be even for f32x2 pairing");
    constexpr int THREADS = (BM / TM) * (BN / TN);
    constexpr int LDA = BM + 4;
    constexpr int LDB = BN + 4;
    constexpr int NA = BM * BK / 4 / THREADS;
    constexpr int NB = BK * BN / 4 / THREADS;
    __shared__ __align__(16) float As[2][BK][LDA];
    __shared__ __align__(16) float Bs[2][BK][LDB];

    const int tid  = threadIdx.x;
    const int brow = blockIdx.y * BM;
    const int bcol = blockIdx.x * BN;
    const int tcol = (tid % (BN / TN)) * TN;
    const int trow = (tid / (BN / TN)) * TM;

    int ar[NA], ac[NA], brr[NB], bcc[NB];
#pragma unroll
    for (int t = 0; t < NA; t++) {
        int f = tid + t * THREADS;
        ar[t] = f / (BK / 4);
        ac[t] = (f % (BK / 4)) * 4;
    }
#pragma unroll
    for (int t = 0; t < NB; t++) {
        int f = tid + t * THREADS;
        brr[t] = f / (BN / 4);
        bcc[t] = (f % (BN / 4)) * 4;
    }

    unsigned long long accp[TM / 2][TN];
#pragma unroll
    for (int m = 0; m < TM / 2; m++)
#pragma unroll
        for (int n = 0; n < TN; n++) accp[m][n] = 0ull;

    float4 afrag[NA], bfrag[NB];

    auto ldg = [&](int k0) {
#pragma unroll
        for (int t = 0; t < NA; t++)
            afrag[t] = *reinterpret_cast<const float4*>(
                &A[(size_t)(brow + ar[t]) * K + k0 + ac[t]]);
#pragma unroll
        for (int t = 0; t < NB; t++)
            bfrag[t] = *reinterpret_cast<const float4*>(
                &B[(size_t)(k0 + brr[t]) * N + bcol + bcc[t]]);
    };
    auto sts = [&](int buf) {
#pragma unroll
        for (int t = 0; t < NA; t++) {
            As[buf][ac[t] + 0][ar[t]] = afrag[t].x;
            As[buf][ac[t] + 1][ar[t]] = afrag[t].y;
            As[buf][ac[t] + 2][ar[t]] = afrag[t].z;
            As[buf][ac[t] + 3][ar[t]] = afrag[t].w;
        }
#pragma unroll
        for (int t = 0; t < NB; t++)
            *reinterpret_cast<float4*>(&Bs[buf][brr[t]][bcc[t]]) = bfrag[t];
    };

    ldg(0);
    sts(0);
    __syncthreads();

    int buf = 0;
    for (int k0 = 0; k0 < K; k0 += BK) {
        const bool has_next = (k0 + BK) < K;
        if (has_next) ldg(k0 + BK);
#pragma unroll
        for (int kk = 0; kk < BK; kk++) {
            unsigned long long rap[TM / 2];
            const unsigned long long* ap =
                reinterpret_cast<const unsigned long long*>(&As[buf][kk][trow]);
#pragma unroll
            for (int m = 0; m < TM / 2; m++) rap[m] = ap[m];
            float rb[TN];
#pragma unroll
            for (int n = 0; n < TN; n += 4)
                *reinterpret_cast<float4*>(&rb[n]) =
                    *reinterpret_cast<const float4*>(&Bs[buf][kk][tcol + n]);
            unsigned long long rbb[TN];
#pragma unroll
            for (int n = 0; n < TN; n++) rbb[n] = bcast2(rb[n]);
#pragma unroll
            for (int m = 0; m < TM / 2; m++)
#pragma unroll
                for (int n = 0; n < TN; n++) fma2(accp[m][n], rap[m], rbb[n]);
        }
        if (has_next) {
            sts(buf ^ 1);
            __syncthreads();
            buf ^= 1;
        }
    }

    float vals[TM][TN];
#pragma unroll
    for (int m = 0; m < TM / 2; m++)
#pragma unroll
        for (int n = 0; n < TN; n++) {
            float2 v = unpack2(accp[m][n]);
            vals[2 * m + 0][n] = v.x;
            vals[2 * m + 1][n] = v.y;
        }

#pragma unroll
    for (int m = 0; m < TM; m++) {
#pragma unroll
        for (int n = 0; n < TN; n += 4) {
            float4 v;
            float* pv = reinterpret_cast<float*>(&v);
#pragma unroll
            for (int q = 0; q < 4; q++) {
                float x = vals[m][n + q];
                if (bias) x += bias[bcol + tcol + n + q];
                if (EPI == 1)  // exact GELU (erf form)
                    x = 0.5f * x * (1.f + erff(x * 0.70710678118654752f));
                pv[q] = x;
            }
            *reinterpret_cast<float4*>(
                &C[(size_t)(brow + trow + m) * N + bcol + tcol + n]) = v;
        }
    }
}

// ---------------- 6) LayerNorm over D=512 (1 block / row) -------------------
__global__ void k_ln(const float* __restrict__ Y, const float* __restrict__ gam,
                     const float* __restrict__ bet, float* __restrict__ out) {
    int row = blockIdx.x;
    const float* y = Y + (size_t)row * Dc;
    int t = threadIdx.x;  // 128 threads
    float v[4];
    float s = 0.f;
#pragma unroll
    for (int i = 0; i < 4; i++) { v[i] = y[t + i * 128]; s += v[i]; }
    __shared__ float red[4];
#pragma unroll
    for (int o = 16; o; o >>= 1) s += __shfl_xor_sync(0xffffffffu, s, o);
    if ((t & 31) == 0) red[t >> 5] = s;
    __syncthreads();
    float mu = (red[0] + red[1] + red[2] + red[3]) * (1.f / Dc);
    __syncthreads();
    float d2 = 0.f;
#pragma unroll
    for (int i = 0; i < 4; i++) { float d = v[i] - mu; d2 += d * d; }
#pragma unroll
    for (int o = 16; o; o >>= 1) d2 += __shfl_xor_sync(0xffffffffu, d2, o);
    if ((t & 31) == 0) red[t >> 5] = d2;
    __syncthreads();
    float var = (red[0] + red[1] + red[2] + red[3]) * (1.f / Dc);
    float rs = rsqrtf(var + 1e-5f);
#pragma unroll
    for (int i = 0; i < 4; i++) {
        int c = t + i * 128;
        out[(size_t)row * Dc + c] = (v[i] - mu) * rs * gam[c] + bet[c];
    }
}

// ---------------- launch -----------------------------------------------------
extern "C" void kernel_launch(void* const* d_in, const int* in_sizes, int n_in,
                              void* d_out, int out_size) {
    const float* x      = (const float*)d_in[0];  // (B,L,E,D)
    const int*   he     = (const int*)  d_in[1];  // (2, nnz)
    const float* lin_w  = (const float*)d_in[2];  // (2, D, D)
    const float* lin_b  = (const float*)d_in[3];  // (2, D)
    const float* comb_w = (const float*)d_in[4];  // (D, D)
    const float* comb_b = (const float*)d_in[5];  // (D,)
    const float* ln_g   = (const float*)d_in[6];
    const float* ln_b   = (const float*)d_in[7];
    float* out = (float*)d_out;
    const int nnz = in_sizes[1] / 2;

    float *p_Wtmp, *p_Wf, *p_z0, *p_y, *p_bf, *p_b1f, *p_partW, *p_partb;
    cudaGetSymbolAddress((void**)&p_Wtmp,  g_Wtmp);
    cudaGetSymbolAddress((void**)&p_Wf,    g_Wf);
    cudaGetSymbolAddress((void**)&p_z0,    g_z0);
    cudaGetSymbolAddress((void**)&p_y,     g_y);
    cudaGetSymbolAddress((void**)&p_bf,    g_bf);
    cudaGetSymbolAddress((void**)&p_b1f,   g_b1f);
    cudaGetSymbolAddress((void**)&p_partW, g_partW);
    cudaGetSymbolAddress((void**)&p_partb, g_partb);

    // 1) mixing vectors (tiny, parallel)
    k_mix<<<1, 128>>>(he, nnz);

    // 2) weighted expert reduce: z0 = sum_u w1[u] * x[:,u,:]
    {
        int total = Gc * (Dc / 4);
        k_reduce<<<(total + 255) / 256, 256>>>(x, p_z0);
    }

    // 3) fold 1 (split-K): Wtmp = W1 @ W2 ; b1f = s2*(b1 @ W2) + b2
    {
        dim3 grid(Dc / 64, Dc / 64, KZ);   // (8, 8, 4) = 256 blocks
        k_fold<<<grid, 256>>>(lin_w, lin_w + Dc * Dc, lin_b, p_partW, p_partb);
        k_comb<<<Dc * Dc / 4 / 256, 256>>>(p_Wtmp, lin_b + Dc, p_b1f, 1);
    }
    // 4) fold 2 (split-K): Wf = Wtmp @ comb_w ; bf = b1f @ comb_w + comb_b
    {
        dim3 grid(Dc / 64, Dc / 64, KZ);
        k_fold<<<grid, 256>>>(p_Wtmp, comb_w, p_b1f, p_partW, p_partb);
        k_comb<<<Dc * Dc / 4 / 256, 256>>>(p_Wf, comb_b, p_bf, 0);
    }

    // 5) main GEMM with bias + exact GELU: y = gelu(z0 @ Wf + bf)
    {
        dim3 grid(Dc / 128, Gc / 128);   // (4, 32) = 128 blocks = 1 wave
        sgemm<128, 128, 16, 8, 8, 1><<<grid, 256>>>(Gc, Dc, Dc, p_z0, p_Wf, p_bf, p_y);
    }

    // 6) LayerNorm -> output
    k_ln<<<Gc, 128>>>(p_y, ln_g, ln_b, out);
}

// round 11
// speedup vs baseline: 3.1636x; 1.2041x over previous
#include <cuda_runtime.h>
#include <cuda_bf16.h>
#include <math.h>
#include <stdint.h>

// Problem constants: B=4, L=1024, E=8, D=512, NLAYERS=2
#define Dc 512
#define Gc 4096   // B*L
#define Ec 8
#define MAXEDGE 256
#define KZ 4      // split-K factor for fold GEMMs
#define KLEN 128  // Dc / KZ

// ---------------- scratch (device globals; no allocations allowed) ----------
__device__ float g_w1[Ec];
__device__ float g_s2;
__device__ __align__(16) float g_partW[KZ * Dc * Dc];
__device__ __align__(16) float g_partb[KZ * Dc];
__device__ __align__(16) float g_Wtmp[Dc*Dc];
__device__ __align__(16) float g_b1f[Dc];
__device__ __align__(16) float g_bf[Dc];
__device__ __align__(16) __nv_bfloat16 g_z0h[Gc*Dc];   // hi(z0)       [m][k]
__device__ __align__(16) __nv_bfloat16 g_z0l[Gc*Dc];   // lo residual  [m][k]
__device__ __align__(16) __nv_bfloat16 g_Wfh[Dc*Dc];   // hi(Wf^T)     [n][k]
__device__ __align__(16) __nv_bfloat16 g_Wfl[Dc*Dc];   // lo(Wf^T)     [n][k]
__device__ __align__(16) float g_y[Gc*Dc];

// ---------------- f32x2 packed helpers (FFMA2, for fold GEMMs) --------------
__device__ __forceinline__ unsigned long long bcast2(float x) {
    unsigned long long r;
    asm("mov.b64 %0, {%1, %1};" : "=l"(r) : "f"(x));
    return r;
}
__device__ __forceinline__ void fma2(unsigned long long& d,
                                     unsigned long long a, unsigned long long b) {
    asm("fma.rn.f32x2 %0, %1, %2, %0;" : "+l"(d) : "l"(a), "l"(b));
}
__device__ __forceinline__ float2 unpack2(unsigned long long p) {
    float2 v;
    asm("mov.b64 {%0, %1}, %2;" : "=f"(v.x), "=f"(v.y) : "l"(p));
    return v;
}

// ---------------- 1) mixing vectors -----------------------------------------
__global__ void k_mix(const int* __restrict__ he, int nnz) {
    __shared__ float M2s[Ec][Ec];
    __shared__ float degn[Ec];
    __shared__ float dege[MAXEDGE];
    __shared__ float Dinv[Ec];
    __shared__ float Binv[MAXEDGE];
    const int* node = he;
    const int* edge = he + nnz;
    int t = threadIdx.x;

    if (t < Ec) degn[t] = 0.f;
    for (int e = t; e < MAXEDGE; e += blockDim.x) dege[e] = 0.f;
    if (t < Ec * Ec) ((float*)M2s)[t] = 0.f;
    __syncthreads();
    for (int i = t; i < nnz; i += blockDim.x) {
        atomicAdd(&degn[node[i]], 1.f);
        atomicAdd(&dege[edge[i]], 1.f);
    }
    __syncthreads();
    if (t < Ec) Dinv[t] = degn[t] > 0.f ? 1.f / degn[t] : 0.f;
    for (int e = t; e < MAXEDGE; e += blockDim.x)
        Binv[e] = dege[e] > 0.f ? 1.f / dege[e] : 0.f;
    __syncthreads();
    int total = nnz * nnz;
    for (int p = t; p < total; p += blockDim.x) {
        int i = p % nnz, j = p / nnz;
        int ei = edge[i];
        if (ei == edge[j])
            atomicAdd(&M2s[node[j]][node[i]], Dinv[node[j]] * Binv[ei]);
    }
    __syncthreads();
    if (t == 0) {
        float w2[Ec], s2 = 0.f;
        for (int u = 0; u < Ec; u++) {
            float s = 0.f;
            for (int v = 0; v < Ec; v++) s += M2s[v][u];
            w2[u] = s / (float)Ec;
            s2 += w2[u];
        }
        for (int q = 0; q < Ec; q++) {
            float s = 0.f;
            for (int u = 0; u < Ec; u++) s += M2s[u][q] * w2[u];
            g_w1[q] = s;
        }
        g_s2 = s2;
    }
}

// ---------------- 2) weighted expert reduce -> split bf16 -------------------
__device__ __forceinline__ unsigned short bfu(__nv_bfloat16 h) {
    return *reinterpret_cast<unsigned short*>(&h);
}
__global__ void k_reduce(const float* __restrict__ X) {
    int i = blockIdx.x * blockDim.x + threadIdx.x;   // over G * (D/4)
    if (i >= Gc * (Dc / 4)) return;
    int g  = i >> 7;
    int d4 = i & 127;
    const float4* xp = reinterpret_cast<const float4*>(X) + (size_t)g * Ec * (Dc / 4) + d4;
    float w[Ec];
#pragma unroll
    for (int u = 0; u < Ec; u++) w[u] = g_w1[u];
    float4 acc = make_float4(0.f, 0.f, 0.f, 0.f);
#pragma unroll
    for (int u = 0; u < Ec; u++) {
        float4 v = xp[(size_t)u * (Dc / 4)];
        acc.x = fmaf(w[u], v.x, acc.x);
        acc.y = fmaf(w[u], v.y, acc.y);
        acc.z = fmaf(w[u], v.z, acc.z);
        acc.w = fmaf(w[u], v.w, acc.w);
    }
    float a[4] = {acc.x, acc.y, acc.z, acc.w};
    unsigned short h[4], l[4];
#pragma unroll
    for (int j = 0; j < 4; j++) {
        __nv_bfloat16 hb = __float2bfloat16(a[j]);
        __nv_bfloat16 lb = __float2bfloat16(a[j] - __bfloat162float(hb));
        h[j] = bfu(hb);
        l[j] = bfu(lb);
    }
    uint2 uh, ul;
    uh.x = (uint32_t)h[0] | ((uint32_t)h[1] << 16);
    uh.y = (uint32_t)h[2] | ((uint32_t)h[3] << 16);
    ul.x = (uint32_t)l[0] | ((uint32_t)l[1] << 16);
    ul.y = (uint32_t)l[2] | ((uint32_t)l[3] << 16);
    *reinterpret_cast<uint2*>(g_z0h + (size_t)i * 4) = uh;
    *reinterpret_cast<uint2*>(g_z0l + (size_t)i * 4) = ul;
}

// ---------------- 3) split-K fold GEMM (fp32, FFMA2) ------------------------
__global__ void __launch_bounds__(256)
k_fold(const float* __restrict__ A, const float* __restrict__ B,
       const float* __restrict__ vsrc,
       float* __restrict__ partW, float* __restrict__ partb) {
    constexpr int BM = 64, BN = 64, BK = 16, TM = 4, TN = 4, THREADS = 256;
    constexpr int LDA = BM + 4, LDB = BN + 4;
    __shared__ __align__(16) float As[2][BK][LDA];
    __shared__ __align__(16) float Bs[2][BK][LDB];
    __shared__ float vsm[KLEN];

    const int tid   = threadIdx.x;
    const int brow  = blockIdx.y * BM;
    const int bcol  = blockIdx.x * BN;
    const int kz    = blockIdx.z;
    const int kbase = kz * KLEN;
    const int tcol  = (tid % (BN / TN)) * TN;
    const int trow  = (tid / (BN / TN)) * TM;
    const int ar = tid / (BK / 4);
    const int ac = (tid % (BK / 4)) * 4;
    const int br = tid / (BN / 4);
    const int bc = (tid % (BN / 4)) * 4;

    for (int i = tid; i < KLEN; i += THREADS) vsm[i] = vsrc[kbase + i];
    const bool bth = (blockIdx.y == 0) && (tid < BN);
    float bacc = 0.f;

    unsigned long long accp[TM / 2][TN];
#pragma unroll
    for (int m = 0; m < TM / 2; m++)
#pragma unroll
        for (int n = 0; n < TN; n++) accp[m][n] = 0ull;

    float4 afrag, bfrag;
    auto ldg = [&](int k0) {
        afrag = *reinterpret_cast<const float4*>(
            &A[(size_t)(brow + ar) * Dc + kbase + k0 + ac]);
        bfrag = *reinterpret_cast<const float4*>(
            &B[(size_t)(kbase + k0 + br) * Dc + bcol + bc]);
    };
    auto sts = [&](int buf) {
        As[buf][ac + 0][ar] = afrag.x;
        As[buf][ac + 1][ar] = afrag.y;
        As[buf][ac + 2][ar] = afrag.z;
        As[buf][ac + 3][ar] = afrag.w;
        *reinterpret_cast<float4*>(&Bs[buf][br][bc]) = bfrag;
    };

    ldg(0);
    sts(0);
    __syncthreads();

    int buf = 0;
    for (int k0 = 0; k0 < KLEN; k0 += BK) {
        const bool has_next = (k0 + BK) < KLEN;
        if (has_next) ldg(k0 + BK);
#pragma unroll
        for (int kk = 0; kk < BK; kk++) {
            unsigned long long rap[TM / 2];
            const unsigned long long* ap =
                reinterpret_cast<const unsigned long long*>(&As[buf][kk][trow]);
#pragma unroll
            for (int m = 0; m < TM / 2; m++) rap[m] = ap[m];
            float rb[TN];
#pragma unroll
            for (int n = 0; n < TN; n += 4)
                *reinterpret_cast<float4*>(&rb[n]) =
                    *reinterpret_cast<const float4*>(&Bs[buf][kk][tcol + n]);
            unsigned long long rbb[TN];
#pragma unroll
            for (int n = 0; n < TN; n++) rbb[n] = bcast2(rb[n]);
#pragma unroll
            for (int m = 0; m < TM / 2; m++)
#pragma unroll
                for (int n = 0; n < TN; n++) fma2(accp[m][n], rap[m], rbb[n]);
        }
        if (bth) {
#pragma unroll 4
            for (int kk = 0; kk < BK; kk++)
                bacc = fmaf(vsm[k0 + kk], Bs[buf][kk][tid], bacc);
        }
        if (has_next) {
            sts(buf ^ 1);
            __syncthreads();
            buf ^= 1;
        }
    }

    if (bth) partb[kz * Dc + bcol + tid] = bacc;
    float* W = partW + (size_t)kz * Dc * Dc;
#pragma unroll
    for (int m = 0; m < TM / 2; m++)
#pragma unroll
        for (int n = 0; n < TN; n++) {
            float2 v = unpack2(accp[m][n]);
            W[(size_t)(brow + trow + 2 * m + 0) * Dc + bcol + tcol + n] = v.x;
            W[(size_t)(brow + trow + 2 * m + 1) * Dc + bcol + tcol + n] = v.y;
        }
}

// ---------------- 4a) combine -> Wtmp fp32 + b1f ----------------------------
__global__ void k_comb1(const float* __restrict__ extra_b) {
    int i = blockIdx.x * blockDim.x + threadIdx.x;   // over Dc*Dc/4
    const float4* p = reinterpret_cast<const float4*>(g_partW);
    constexpr int STRIDE = Dc * Dc / 4;
    float4 a = p[i], b = p[i + STRIDE], c = p[i + 2 * STRIDE], d = p[i + 3 * STRIDE];
    float4 r;
    r.x = ((a.x + b.x) + c.x) + d.x;
    r.y = ((a.y + b.y) + c.y) + d.y;
    r.z = ((a.z + b.z) + c.z) + d.z;
    r.w = ((a.w + b.w) + c.w) + d.w;
    reinterpret_cast<float4*>(g_Wtmp)[i] = r;
    if (i < Dc) {
        float s = ((g_partb[i] + g_partb[Dc + i]) + g_partb[2 * Dc + i])
                  + g_partb[3 * Dc + i];
        g_b1f[i] = g_s2 * s + extra_b[i];
    }
}

// ---------------- 4b) combine -> Wf^T split-bf16 + bf -----------------------
__global__ void k_comb2(const float* __restrict__ extra_b) {
    int i = blockIdx.x * blockDim.x + threadIdx.x;   // over Dc*Dc/4
    const float4* p = reinterpret_cast<const float4*>(g_partW);
    constexpr int STRIDE = Dc * Dc / 4;
    float4 a = p[i], b = p[i + STRIDE], c = p[i + 2 * STRIDE], d = p[i + 3 * STRIDE];
    float r[4];
    r[0] = ((a.x + b.x) + c.x) + d.x;
    r[1] = ((a.y + b.y) + c.y) + d.y;
    r[2] = ((a.z + b.z) + c.z) + d.z;
    r[3] = ((a.w + b.w) + c.w) + d.w;
    int k = i >> 7;            // Wf row (K index of main GEMM)
    int n = (i & 127) * 4;     // Wf col (N index) -> transposed row
#pragma unroll
    for (int j = 0; j < 4; j++) {
        __nv_bfloat16 hb = __float2bfloat16(r[j]);
        __nv_bfloat16 lb = __float2bfloat16(r[j] - __bfloat162float(hb));
        g_Wfh[(size_t)(n + j) * Dc + k] = hb;
        g_Wfl[(size_t)(n + j) * Dc + k] = lb;
    }
    if (i < Dc) {
        float s = ((g_partb[i] + g_partb[Dc + i]) + g_partb[2 * Dc + i])
                  + g_partb[3 * Dc + i];
        g_bf[i] = s + extra_b[i];
    }
}

// ---------------- 5) main GEMM: mma.sync bf16-split (sm_100-safe) -----------
// y = gelu(z0 @ Wf + bf), z0 split hi/lo [m][k], Wf^T split hi/lo [n][k].
// CTA 128x128, 8 warps as 4(m) x 2(n), warp tile 32x64.
// BK=16, double-buffered smem (rows padded to 24 bf16 = 48B, conflict-free).
#define MM_BK   16
#define MM_LDK  24                      // padded row length (bf16 elems)
#define MM_TILE (128 * MM_LDK)          // one 128-row tile, elems
#define MM_BUF  (4 * MM_TILE)           // Ah,Al,Bh,Bl per buffer
#define MM_SMEM (2 * MM_BUF * 2)        // bytes (bf16=2B, double buffer)

__device__ __forceinline__ void mma16816(float* c, uint32_t a0, uint32_t a1,
                                         uint32_t a2, uint32_t a3,
                                         uint32_t b0, uint32_t b1) {
    asm volatile(
        "mma.sync.aligned.m16n8k16.row.col.f32.bf16.bf16.f32 "
        "{%0,%1,%2,%3}, {%4,%5,%6,%7}, {%8,%9}, {%0,%1,%2,%3};"
        : "+f"(c[0]), "+f"(c[1]), "+f"(c[2]), "+f"(c[3])
        : "r"(a0), "r"(a1), "r"(a2), "r"(a3), "r"(b0), "r"(b1));
}

__global__ void __launch_bounds__(256, 1) k_main_mma() {
    extern __shared__ __nv_bfloat16 sm[];
    const int tid  = threadIdx.x;
    const int lane = tid & 31;
    const int wid  = tid >> 5;
    const int wm   = wid >> 1;          // 0..3 -> m offset wm*32
    const int wn   = wid & 1;           // 0..1 -> n offset wn*64
    const int brow = blockIdx.y * 128;
    const int bcol = blockIdx.x * 128;
    const int g    = lane >> 2;         // 0..7
    const int tg   = lane & 3;          // 0..3

    // per-thread global/smem load coords: 128 rows x 4 chunks (8B), 2 iters
    const int r0 = tid >> 2,  c0 = (tid & 3) * 4;
    const int r1 = r0 + 64;             // (tid+256)>>2

    float acc[2][8][4];
#pragma unroll
    for (int mf = 0; mf < 2; mf++)
#pragma unroll
        for (int nf = 0; nf < 8; nf++)
#pragma unroll
            for (int q = 0; q < 4; q++) acc[mf][nf][q] = 0.f;

    uint2 pf[8];
    auto ldg = [&](int kb) {
        const __nv_bfloat16* s;
        s = g_z0h + (size_t)(brow + r0) * Dc + kb;  pf[0] = *(const uint2*)(s + c0);
        s = g_z0h + (size_t)(brow + r1) * Dc + kb;  pf[1] = *(const uint2*)(s + c0);
        s = g_z0l + (size_t)(brow + r0) * Dc + kb;  pf[2] = *(const uint2*)(s + c0);
        s = g_z0l + (size_t)(brow + r1) * Dc + kb;  pf[3] = *(const uint2*)(s + c0);
        s = g_Wfh + (size_t)(bcol + r0) * Dc + kb;  pf[4] = *(const uint2*)(s + c0);
        s = g_Wfh + (size_t)(bcol + r1) * Dc + kb;  pf[5] = *(const uint2*)(s + c0);
        s = g_Wfl + (size_t)(bcol + r0) * Dc + kb;  pf[6] = *(const uint2*)(s + c0);
        s = g_Wfl + (size_t)(bcol + r1) * Dc + kb;  pf[7] = *(const uint2*)(s + c0);
    };
    auto sts = [&](int buf) {
        __nv_bfloat16* base = sm + buf * MM_BUF;
#pragma unroll
        for (int a = 0; a < 4; a++) {
            *(uint2*)(base + a * MM_TILE + r0 * MM_LDK + c0) = pf[2 * a + 0];
            *(uint2*)(base + a * MM_TILE + r1 * MM_LDK + c0) = pf[2 * a + 1];
        }
    };

    ldg(0);
    sts(0);
    __syncthreads();

    int buf = 0;
    for (int kt = 0; kt < Dc / MM_BK; kt++) {
        const bool has_next = (kt + 1) < (Dc / MM_BK);
        if (has_next) ldg((kt + 1) * MM_BK);

        const __nv_bfloat16* sAh = sm + buf * MM_BUF + 0 * MM_TILE;
        const __nv_bfloat16* sAl = sm + buf * MM_BUF + 1 * MM_TILE;
        const __nv_bfloat16* sBh = sm + buf * MM_BUF + 2 * MM_TILE;
        const __nv_bfloat16* sBl = sm + buf * MM_BUF + 3 * MM_TILE;

        // A fragments (m16 x k16), rows wm*32 + mf*16
        uint32_t Ah[2][4], Al[2][4];
#pragma unroll
        for (int mf = 0; mf < 2; mf++) {
            const __nv_bfloat16* p = sAh + (wm * 32 + mf * 16 + g) * MM_LDK + tg * 2;
            Ah[mf][0] = *(const uint32_t*)(p);
            Ah[mf][1] = *(const uint32_t*)(p + 8 * MM_LDK);
            Ah[mf][2] = *(const uint32_t*)(p + 8);
            Ah[mf][3] = *(const uint32_t*)(p + 8 * MM_LDK + 8);
            const __nv_bfloat16* q = sAl + (wm * 32 + mf * 16 + g) * MM_LDK + tg * 2;
            Al[mf][0] = *(const uint32_t*)(q);
            Al[mf][1] = *(const uint32_t*)(q + 8 * MM_LDK);
            Al[mf][2] = *(const uint32_t*)(q + 8);
            Al[mf][3] = *(const uint32_t*)(q + 8 * MM_LDK + 8);
        }
        // B fragments (k16 x n8), B stored [n][k] = col-major of kxn
        uint32_t Bh[8][2], Bl[8][2];
#pragma unroll
        for (int nf = 0; nf < 8; nf++) {
            const __nv_bfloat16* p = sBh + (wn * 64 + nf * 8 + g) * MM_LDK + tg * 2;
            Bh[nf][0] = *(const uint32_t*)(p);
            Bh[nf][1] = *(const uint32_t*)(p + 8);
            const __nv_bfloat16* q = sBl + (wn * 64 + nf * 8 + g) * MM_LDK + tg * 2;
            Bl[nf][0] = *(const uint32_t*)(q);
            Bl[nf][1] = *(const uint32_t*)(q + 8);
        }
#pragma unroll
        for (int mf = 0; mf < 2; mf++)
#pragma unroll
            for (int nf = 0; nf < 8; nf++) {
                mma16816(acc[mf][nf], Ah[mf][0], Ah[mf][1], Ah[mf][2], Ah[mf][3],
                         Bh[nf][0], Bh[nf][1]);
                mma16816(acc[mf][nf], Ah[mf][0], Ah[mf][1], Ah[mf][2], Ah[mf][3],
                         Bl[nf][0], Bl[nf][1]);
                mma16816(acc[mf][nf], Al[mf][0], Al[mf][1], Al[mf][2], Al[mf][3],
                         Bh[nf][0], Bh[nf][1]);
            }

        if (has_next) {
            sts(buf ^ 1);
            __syncthreads();
            buf ^= 1;
        }
    }

    // epilogue: bias + exact GELU
    // C frag map: (c0,c1) -> row g,   cols tg*2, tg*2+1
    //             (c2,c3) -> row g+8, cols tg*2, tg*2+1
#pragma unroll
    for (int mf = 0; mf < 2; mf++) {
#pragma unroll
        for (int nf = 0; nf < 8; nf++) {
            int mbase = brow + wm * 32 + mf * 16 + g;
            int nbase = bcol + wn * 64 + nf * 8 + tg * 2;
            float b0v = g_bf[nbase], b1v = g_bf[nbase + 1];
            float x0 = acc[mf][nf][0] + b0v;
            float x1 = acc[mf][nf][1] + b1v;
            float x2 = acc[mf][nf][2] + b0v;
            float x3 = acc[mf][nf][3] + b1v;
            float2 lo, hi;
            lo.x = 0.5f * x0 * (1.f + erff(x0 * 0.70710678118654752f));
            lo.y = 0.5f * x1 * (1.f + erff(x1 * 0.70710678118654752f));
            hi.x = 0.5f * x2 * (1.f + erff(x2 * 0.70710678118654752f));
            hi.y = 0.5f * x3 * (1.f + erff(x3 * 0.70710678118654752f));
            *reinterpret_cast<float2*>(g_y + (size_t)mbase * Dc + nbase) = lo;
            *reinterpret_cast<float2*>(g_y + (size_t)(mbase + 8) * Dc + nbase) = hi;
        }
    }
}

// ---------------- 6) LayerNorm over D=512 -----------------------------------
__global__ void k_ln(const float* __restrict__ Y, const float* __restrict__ gam,
                     const float* __restrict__ bet, float* __restrict__ out) {
    int row = blockIdx.x;
    const float* y = Y + (size_t)row * Dc;
    int t = threadIdx.x;
    float v[4];
    float s = 0.f;
#pragma unroll
    for (int i = 0; i < 4; i++) { v[i] = y[t + i * 128]; s += v[i]; }
    __shared__ float red[4];
#pragma unroll
    for (int o = 16; o; o >>= 1) s += __shfl_xor_sync(0xffffffffu, s, o);
    if ((t & 31) == 0) red[t >> 5] = s;
    __syncthreads();
    float mu = (red[0] + red[1] + red[2] + red[3]) * (1.f / Dc);
    __syncthreads();
    float d2 = 0.f;
#pragma unroll
    for (int i = 0; i < 4; i++) { float d = v[i] - mu; d2 += d * d; }
#pragma unroll
    for (int o = 16; o; o >>= 1) d2 += __shfl_xor_sync(0xffffffffu, d2, o);
    if ((t & 31) == 0) red[t >> 5] = d2;
    __syncthreads();
    float var = (red[0] + red[1] + red[2] + red[3]) * (1.f / Dc);
    float rs = rsqrtf(var + 1e-5f);
#pragma unroll
    for (int i = 0; i < 4; i++) {
        int c = t + i * 128;
        out[(size_t)row * Dc + c] = (v[i] - mu) * rs * gam[c] + bet[c];
    }
}

// ---------------- launch -----------------------------------------------------
extern "C" void kernel_launch(void* const* d_in, const int* in_sizes, int n_in,
                              void* d_out, int out_size) {
    const float* x      = (const float*)d_in[0];
    const int*   he     = (const int*)  d_in[1];
    const float* lin_w  = (const float*)d_in[2];
    const float* lin_b  = (const float*)d_in[3];
    const float* comb_w = (const float*)d_in[4];
    const float* comb_b = (const float*)d_in[5];
    const float* ln_g   = (const float*)d_in[6];
    const float* ln_b   = (const float*)d_in[7];
    float* out = (float*)d_out;
    const int nnz = in_sizes[1] / 2;

    float *p_Wtmp, *p_y, *p_b1f, *p_partW, *p_partb;
    cudaGetSymbolAddress((void**)&p_Wtmp,  g_Wtmp);
    cudaGetSymbolAddress((void**)&p_y,     g_y);
    cudaGetSymbolAddress((void**)&p_b1f,   g_b1f);
    cudaGetSymbolAddress((void**)&p_partW, g_partW);
    cudaGetSymbolAddress((void**)&p_partb, g_partb);

    cudaFuncSetAttribute(k_main_mma,
                         cudaFuncAttributeMaxDynamicSharedMemorySize, MM_SMEM);

    // 1) mixing vectors
    k_mix<<<1, 128>>>(he, nnz);

    // 2) weighted expert reduce -> z0 split bf16
    {
        int total = Gc * (Dc / 4);
        k_reduce<<<(total + 255) / 256, 256>>>(x);
    }

    // 3) fold 1 (split-K): Wtmp = W1 @ W2 ; b1f = s2*(b1 @ W2) + b2
    {
        dim3 grid(Dc / 64, Dc / 64, KZ);
        k_fold<<<grid, 256>>>(lin_w, lin_w + Dc * Dc, lin_b, p_partW, p_partb);
        k_comb1<<<Dc * Dc / 4 / 256, 256>>>(lin_b + Dc);
    }
    // 4) fold 2 (split-K): Wf = Wtmp @ comb_w -> transposed split-bf16 ; bf
    {
        dim3 grid(Dc / 64, Dc / 64, KZ);
        k_fold<<<grid, 256>>>(p_Wtmp, comb_w, p_b1f, p_partW, p_partb);
        k_comb2<<<Dc * Dc / 4 / 256, 256>>>(comb_b);
    }

    // 5) main GEMM on tensor cores (mma.sync): y = gelu(z0 @ Wf + bf)
    {
        dim3 grid(Dc / 128, Gc / 128);   // (4, 32) = 128 CTAs = 1 wave
        k_main_mma<<<grid, 256, MM_SMEM>>>();
    }

    // 6) LayerNorm -> output
    k_ln<<<Gc, 128>>>(p_y, ln_g, ln_b, out);
}